// round 1
// baseline (speedup 1.0000x reference)
#include <cuda_runtime.h>

#define EPS 1e-5f

// dims (fixed per reference)
#define Nn 8
#define Cc 256
#define Hh 64
#define Ww 64
#define HW 4096
#define OC 64
#define Pp 36

// softmax weights scratch: [n][pixel][36]  (4.5 MB)
__device__ float g_wts[(size_t)Nn * HW * Pp];

typedef unsigned long long u64;

__device__ __forceinline__ u64 pack2(float x, float y) {
    u64 r; asm("mov.b64 %0, {%1,%2};" : "=l"(r) : "f"(x), "f"(y)); return r;
}
__device__ __forceinline__ void fma2(u64 &d, u64 a, u64 b) {
    asm("fma.rn.f32x2 %0, %1, %2, %0;" : "+l"(d) : "l"(a), "l"(b));
}
__device__ __forceinline__ float2 unpack2(u64 v) {
    float2 r; asm("mov.b64 {%0,%1}, %2;" : "=f"(r.x), "=f"(r.y) : "l"(v)); return r;
}

// ---------------------------------------------------------------------------
// Kernel 1: per-pixel weight computation.
// Block: one n, 128 contiguous flat pixels. 256 threads.
// smem: xs[256][128] (131072 B) | w0s[64][256] (65536 B) | ys[64][128] (32768 B)
// phase3 aliases w1s[36][64] over xs.
// ---------------------------------------------------------------------------
extern "C" __global__ void __launch_bounds__(256, 1)
k_weights(const float* __restrict__ x,
          const float* __restrict__ w0, const float* __restrict__ b0,
          const float* __restrict__ bn0_g, const float* __restrict__ bn0_b,
          const float* __restrict__ bn0_m, const float* __restrict__ bn0_v,
          const float* __restrict__ w1, const float* __restrict__ b1,
          const float* __restrict__ bn1_g, const float* __restrict__ bn1_b,
          const float* __restrict__ bn1_m, const float* __restrict__ bn1_v)
{
    extern __shared__ char smem[];
    float* xs  = (float*)smem;              // 256 x 128
    float* w0s = (float*)(smem + 131072);   // 64 x 256
    float* ys  = (float*)(smem + 196608);   // 64 x 128
    float* w1s = (float*)smem;              // alias (phase 3): 36 x 64

    const int tid = threadIdx.x;
    const int n   = blockIdx.y;
    const int p0  = blockIdx.x * 128;

    // ---- stage x columns: xs[c][p] ----
    const float* xn = x + (size_t)n * Cc * HW + p0;
    #pragma unroll 4
    for (int i = tid; i < 256 * 32; i += 256) {      // float4 granularity
        int c = i >> 5, p4 = i & 31;
        ((float4*)xs)[c * 32 + p4] = *(const float4*)(xn + (size_t)c * HW + p4 * 4);
    }
    // ---- stage w0 [oc][c] ----
    #pragma unroll 4
    for (int i = tid; i < (OC * Cc) / 4; i += 256)
        ((float4*)w0s)[i] = ((const float4*)w0)[i];
    __syncthreads();

    // ---- phase 2: layer0 GEMM, 4oc x 8px per thread, f32x2 packed ----
    const int ocb = tid >> 4;   // 0..15 -> oc group of 4
    const int pxb = tid & 15;   // 0..15 -> px group of 8
    u64 acc[4][4];
    #pragma unroll
    for (int i = 0; i < 4; i++)
        #pragma unroll
        for (int j = 0; j < 4; j++) acc[i][j] = 0ULL;

    #pragma unroll 2
    for (int c = 0; c < Cc; c++) {
        const float* xr = xs + c * 128 + pxb * 8;
        float4 xa = *(const float4*)xr;
        float4 xb = *(const float4*)(xr + 4);
        u64 xp[4] = { pack2(xa.x, xa.y), pack2(xa.z, xa.w),
                      pack2(xb.x, xb.y), pack2(xb.z, xb.w) };
        #pragma unroll
        for (int i = 0; i < 4; i++) {
            float wv = w0s[(ocb * 4 + i) * 256 + c];
            u64 wp = pack2(wv, wv);
            #pragma unroll
            for (int j = 0; j < 4; j++) fma2(acc[i][j], wp, xp[j]);
        }
    }
    // epilogue: bias + BN + ReLU -> ys
    #pragma unroll
    for (int i = 0; i < 4; i++) {
        int oc = ocb * 4 + i;
        float A0 = bn0_g[oc] * rsqrtf(bn0_v[oc] + EPS);
        float B0 = (b0[oc] - bn0_m[oc]) * A0 + bn0_b[oc];
        #pragma unroll
        for (int j = 0; j < 4; j++) {
            float2 v = unpack2(acc[i][j]);
            ys[oc * 128 + pxb * 8 + 2 * j]     = fmaxf(fmaf(v.x, A0, B0), 0.f);
            ys[oc * 128 + pxb * 8 + 2 * j + 1] = fmaxf(fmaf(v.y, A0, B0), 0.f);
        }
    }
    __syncthreads();

    // ---- stage w1 (aliases xs region; xs no longer needed) ----
    for (int i = tid; i < (Pp * OC) / 4; i += 256)
        ((float4*)w1s)[i] = ((const float4*)w1)[i];
    __syncthreads();

    // ---- phase 3: encoder + BN + ReLU + softmax over k (9) per (px, u) ----
    const int px = tid & 127;
    const int uA = tid >> 7;        // 0 or 1
    const int uB = uA + 2;          // 2 or 3

    float accA[9], accB[9];
    #pragma unroll
    for (int k = 0; k < 9; k++) { accA[k] = 0.f; accB[k] = 0.f; }

    #pragma unroll 2
    for (int o = 0; o < OC; o++) {
        float yo = ys[o * 128 + px];
        #pragma unroll
        for (int k = 0; k < 9; k++) {
            accA[k] = fmaf(w1s[(k * 4 + uA) * OC + o], yo, accA[k]);
            accB[k] = fmaf(w1s[(k * 4 + uB) * OC + o], yo, accB[k]);
        }
    }

    float* dst = g_wts + (size_t)(n * HW + p0 + px) * Pp;

    // u = uA
    {
        float e[9]; float mx = -1e30f;
        #pragma unroll
        for (int k = 0; k < 9; k++) {
            int pch = k * 4 + uA;
            float A1 = bn1_g[pch] * rsqrtf(bn1_v[pch] + EPS);
            float B1 = (b1[pch] - bn1_m[pch]) * A1 + bn1_b[pch];
            float v = fmaxf(fmaf(accA[k], A1, B1), 0.f);
            e[k] = v; mx = fmaxf(mx, v);
        }
        float s = 0.f;
        #pragma unroll
        for (int k = 0; k < 9; k++) { float t = __expf(e[k] - mx); e[k] = t; s += t; }
        float inv = 1.f / s;
        #pragma unroll
        for (int k = 0; k < 9; k++) dst[k * 4 + uA] = e[k] * inv;
    }
    // u = uB
    {
        float e[9]; float mx = -1e30f;
        #pragma unroll
        for (int k = 0; k < 9; k++) {
            int pch = k * 4 + uB;
            float A1 = bn1_g[pch] * rsqrtf(bn1_v[pch] + EPS);
            float B1 = (b1[pch] - bn1_m[pch]) * A1 + bn1_b[pch];
            float v = fmaxf(fmaf(accB[k], A1, B1), 0.f);
            e[k] = v; mx = fmaxf(mx, v);
        }
        float s = 0.f;
        #pragma unroll
        for (int k = 0; k < 9; k++) { float t = __expf(e[k] - mx); e[k] = t; s += t; }
        float inv = 1.f / s;
        #pragma unroll
        for (int k = 0; k < 9; k++) dst[k * 4 + uB] = e[k] * inv;
    }
}

// ---------------------------------------------------------------------------
// Kernel 2: reassembly + pixelshuffle.
// Block: 8(h) x 32(w) pixel tile, 64 channels (c-split of 4), one n.
// Each thread owns one pixel: 36 weights in registers (f32x2 packed),
// loops channels in 8-channel smem halo chunks, emits 2x float2 per channel.
// ---------------------------------------------------------------------------
extern "C" __global__ void __launch_bounds__(256)
k_reassemble(const float* __restrict__ x, float* __restrict__ out)
{
    __shared__ float xs[8][10][34];

    const int tx  = threadIdx.x & 31;
    const int ty  = threadIdx.x >> 5;
    const int w0p = blockIdx.x * 32;
    const int h0  = blockIdx.y * 8;
    const int n   = blockIdx.z >> 2;
    const int c0  = (blockIdx.z & 3) * 64;
    const int h   = h0 + ty;
    const int w   = w0p + tx;

    // load this pixel's 36 softmax weights into registers, f32x2-packed
    const float4* wp4 = (const float4*)(g_wts + (size_t)(n * HW + h * Ww + w) * Pp);
    u64 wp01[9], wp23[9];
    #pragma unroll
    for (int k = 0; k < 9; k++) {
        float4 v = wp4[k];
        wp01[k] = pack2(v.x, v.y);   // u=0, u=1
        wp23[k] = pack2(v.z, v.w);   // u=2, u=3
    }

    const float* xb = x   + (size_t)n * Cc * HW;
    float*       ob = out + (size_t)n * Cc * (HW * 4);

    for (int ch = 0; ch < 64; ch += 8) {
        __syncthreads();   // protect previous chunk's smem
        // cooperative halo load: 8 channels x 10 x 34
        for (int e = threadIdx.x; e < 8 * 10 * 34; e += 256) {
            int cl = e / 340, r = e % 340;
            int row = r / 34, col = r % 34;
            int gh = h0 - 1 + row, gw = w0p - 1 + col;
            float v = 0.f;
            if ((unsigned)gh < (unsigned)Hh && (unsigned)gw < (unsigned)Ww)
                v = xb[(size_t)(c0 + ch + cl) * HW + gh * Ww + gw];
            xs[cl][row][col] = v;
        }
        __syncthreads();

        #pragma unroll
        for (int cl = 0; cl < 8; cl++) {
            int c = c0 + ch + cl;
            u64 a01 = 0ULL, a23 = 0ULL;
            #pragma unroll
            for (int dy = 0; dy < 3; dy++) {
                #pragma unroll
                for (int dx = 0; dx < 3; dx++) {
                    float xv = xs[cl][ty + dy][tx + dx];
                    u64 xp = pack2(xv, xv);
                    int k = dy * 3 + dx;
                    fma2(a01, xp, wp01[k]);
                    fma2(a23, xp, wp23[k]);
                }
            }
            float* op = ob + (size_t)c * (HW * 4) + (2 * h) * 128 + 2 * w;
            *(float2*)op          = unpack2(a01);   // row 2h:   (u=0, u=1)
            *(float2*)(op + 128)  = unpack2(a23);   // row 2h+1: (u=2, u=3)
        }
    }
}

extern "C" void kernel_launch(void* const* d_in, const int* in_sizes, int n_in,
                              void* d_out, int out_size)
{
    const float* x     = (const float*)d_in[0];
    const float* w0    = (const float*)d_in[1];
    const float* b0    = (const float*)d_in[2];
    const float* bn0_g = (const float*)d_in[3];
    const float* bn0_b = (const float*)d_in[4];
    const float* bn0_m = (const float*)d_in[5];
    const float* bn0_v = (const float*)d_in[6];
    const float* w1    = (const float*)d_in[7];
    const float* b1    = (const float*)d_in[8];
    const float* bn1_g = (const float*)d_in[9];
    const float* bn1_b = (const float*)d_in[10];
    const float* bn1_m = (const float*)d_in[11];
    const float* bn1_v = (const float*)d_in[12];
    float* out = (float*)d_out;

    const int SMEM1 = 131072 + 65536 + 32768;   // 229376 B
    cudaFuncSetAttribute(k_weights, cudaFuncAttributeMaxDynamicSharedMemorySize, SMEM1);

    dim3 g1(32, Nn);          // 128 pixels/block
    k_weights<<<g1, 256, SMEM1>>>(x, w0, b0, bn0_g, bn0_b, bn0_m, bn0_v,
                                  w1, b1, bn1_g, bn1_b, bn1_m, bn1_v);

    dim3 g2(2, 8, Nn * 4);    // (w tiles, h tiles, n * c-split)
    k_reassemble<<<g2, 256>>>(x, out);
}

// round 2
// speedup vs baseline: 1.3033x; 1.3033x over previous
#include <cuda_runtime.h>

#define EPS 1e-5f

#define Nn 8
#define Cc 256
#define Hh 64
#define Ww 64
#define HW 4096
#define OC 64
#define Pp 36

typedef unsigned long long u64;
typedef unsigned int u32;

// ---- device scratch (allowed: static __device__ arrays) ----
__device__ float g_wts[(size_t)Nn * HW * Pp];     // softmax weights [n][px][36]
__device__ float g_w0t[Cc * OC];                  // w0 transposed [c][oc]
__device__ u64   g_w1p[2 * 9 * OC];               // packed w1 pairs [h][k][o] = (u=h, u=h+2)
__device__ float g_A0[OC], g_B0[OC];              // folded BN0 (scale, bias incl conv bias)
__device__ float g_A1[Pp], g_B1[Pp];              // folded BN1

__device__ __forceinline__ u64 pack2(float x, float y) {
    u64 r; asm("mov.b64 %0, {%1,%2};" : "=l"(r) : "f"(x), "f"(y)); return r;
}
__device__ __forceinline__ void fma2(u64 &d, u64 a, u64 b) {
    asm("fma.rn.f32x2 %0, %1, %2, %0;" : "+l"(d) : "l"(a), "l"(b));
}
__device__ __forceinline__ float2 unpack2(u64 v) {
    float2 r; asm("mov.b64 {%0,%1}, %2;" : "=f"(r.x), "=f"(r.y) : "l"(v)); return r;
}

// ---------------------------------------------------------------------------
// Prep kernel: transpose w0, fold BN constants, pack w1 pairs. Tiny.
// ---------------------------------------------------------------------------
extern "C" __global__ void k_prep(const float* __restrict__ w0, const float* __restrict__ b0,
                                  const float* __restrict__ bn0_g, const float* __restrict__ bn0_b,
                                  const float* __restrict__ bn0_m, const float* __restrict__ bn0_v,
                                  const float* __restrict__ w1, const float* __restrict__ b1,
                                  const float* __restrict__ bn1_g, const float* __restrict__ bn1_b,
                                  const float* __restrict__ bn1_m, const float* __restrict__ bn1_v)
{
    int i = blockIdx.x * blockDim.x + threadIdx.x;
    if (i < Cc * OC) {
        int oc = i >> 8, c = i & 255;       // coalesced read of w0[oc][c]
        g_w0t[c * OC + oc] = w0[i];
    }
    if (i < OC) {
        float A = bn0_g[i] * rsqrtf(bn0_v[i] + EPS);
        g_A0[i] = A;
        g_B0[i] = (b0[i] - bn0_m[i]) * A + bn0_b[i];
    }
    if (i < Pp) {
        float A = bn1_g[i] * rsqrtf(bn1_v[i] + EPS);
        g_A1[i] = A;
        g_B1[i] = (b1[i] - bn1_m[i]) * A + bn1_b[i];
    }
    if (i < 2 * 9 * OC) {
        int h = i / (9 * OC), k = (i / OC) % 9, o = i % OC;
        g_w1p[i] = pack2(w1[(4 * k + h) * OC + o], w1[(4 * k + h + 2) * OC + o]);
    }
}

// ---------------------------------------------------------------------------
// Kernel 1: per-pixel weight computation. 512 threads, 256 px per block.
// smem layout (bytes):
//   [0      , 65536 )  w0s [256k][64oc]   (aliased by wts_s [256px][37] in phase 4)
//   [65536  , 98304 )  xs  [2][16k][256px] double buffer
//   [98304  , 164096)  ys  [64oc][257px padded]
//   [164096 , 173312)  w1p [2][9][64] u64
// ---------------------------------------------------------------------------
#define OFF_W0  0
#define OFF_XS  65536
#define OFF_YS  98304
#define OFF_W1P 164096
#define SMEM1   173312
#define YSTRIDE 257

extern "C" __global__ void __launch_bounds__(512, 1)
k_weights(const float* __restrict__ x)
{
    extern __shared__ char smem[];
    float* w0s  = (float*)(smem + OFF_W0);
    float* ys   = (float*)(smem + OFF_YS);
    u64*   w1ps = (u64*)  (smem + OFF_W1P);
    float* wts_s = (float*)(smem + OFF_W0);   // phase-4 alias

    const int t  = threadIdx.x;
    const int n  = blockIdx.y;
    const int p0 = blockIdx.x * 256;

    const float* xn = x + (size_t)n * Cc * HW + p0;

    // prefetch chunk 0 into registers (c = t/32, px = (t%32)*8)
    const int lc = t >> 5;          // warp id = c row within chunk
    const int lp = (t & 31) * 8;    // px offset
    float4 ra = *(const float4*)(xn + (size_t)lc * HW + lp);
    float4 rb = *(const float4*)(xn + (size_t)lc * HW + lp + 4);

    // stage w1p (early, overlaps)
    for (int i = t; i < 2 * 9 * OC; i += 512) w1ps[i] = g_w1p[i];
    // stage w0s (prepacked/transposed) — straight float4 copy
    #pragma unroll
    for (int i = 0; i < 8; i++)
        ((float4*)w0s)[i * 512 + t] = ((const float4*)g_w0t)[i * 512 + t];

    // ---- phase 2: GEMM 64oc x 256px, k-chunks of 16, double buffered ----
    const int ocg = t & 7;          // oc group: oc = ocg*8 .. +7
    const int pxg = t >> 3;         // px group: px = pxg*4 .. +3 (0..63)

    u64 acc[4][4];
    #pragma unroll
    for (int i = 0; i < 4; i++)
        #pragma unroll
        for (int j = 0; j < 4; j++) acc[i][j] = 0ULL;

    const char* wbase = smem + OFF_W0 + ocg * 32;
    const char* xbase = smem + OFF_XS + pxg * 16;

    for (int kc = 0; kc < 16; kc++) {
        // store prefetched regs into buffer kc&1
        float* xb = (float*)(smem + OFF_XS + (kc & 1) * 16384);
        *(float4*)(xb + lc * 256 + lp)     = ra;
        *(float4*)(xb + lc * 256 + lp + 4) = rb;
        __syncthreads();
        if (kc < 15) {  // prefetch next chunk (overlaps compute)
            const float* src = xn + (size_t)((kc + 1) * 16 + lc) * HW + lp;
            ra = *(const float4*)src;
            rb = *(const float4*)(src + 4);
        }
        const char* wp = wbase + (size_t)kc * 16 * 256;
        const char* xp = xbase + (kc & 1) * 16384;
        #pragma unroll
        for (int kk = 0; kk < 16; kk++) {
            ulonglong2 wA = *(const ulonglong2*)(wp + kk * 256);
            ulonglong2 wB = *(const ulonglong2*)(wp + kk * 256 + 16);
            float4 xv = *(const float4*)(xp + kk * 1024);
            u64 x0 = pack2(xv.x, xv.x), x1 = pack2(xv.y, xv.y);
            u64 x2 = pack2(xv.z, xv.z), x3 = pack2(xv.w, xv.w);
            fma2(acc[0][0], wA.x, x0); fma2(acc[0][1], wA.x, x1);
            fma2(acc[0][2], wA.x, x2); fma2(acc[0][3], wA.x, x3);
            fma2(acc[1][0], wA.y, x0); fma2(acc[1][1], wA.y, x1);
            fma2(acc[1][2], wA.y, x2); fma2(acc[1][3], wA.y, x3);
            fma2(acc[2][0], wB.x, x0); fma2(acc[2][1], wB.x, x1);
            fma2(acc[2][2], wB.x, x2); fma2(acc[2][3], wB.x, x3);
            fma2(acc[3][0], wB.y, x0); fma2(acc[3][1], wB.y, x1);
            fma2(acc[3][2], wB.y, x2); fma2(acc[3][3], wB.y, x3);
        }
        // buffer reuse hazard covered by next iteration's __syncthreads()
    }

    // ---- epilogue: BN + ReLU -> ys ----
    #pragma unroll
    for (int i = 0; i < 4; i++) {
        int oc0 = ocg * 8 + 2 * i, oc1 = oc0 + 1;
        float Aa = g_A0[oc0], Ba = g_B0[oc0];
        float Ab = g_A0[oc1], Bb = g_B0[oc1];
        #pragma unroll
        for (int j = 0; j < 4; j++) {
            int px = pxg * 4 + j;
            float2 v = unpack2(acc[i][j]);
            ys[oc0 * YSTRIDE + px] = fmaxf(fmaf(v.x, Aa, Ba), 0.f);
            ys[oc1 * YSTRIDE + px] = fmaxf(fmaf(v.y, Ab, Bb), 0.f);
        }
    }
    __syncthreads();

    // ---- phase 3: encoder (9k x 2u per thread, f32x2 over (u, u+2)) ----
    const int px = t & 255;
    const int hh = t >> 8;          // 0 -> u {0,2}, 1 -> u {1,3}
    const u64* wrow = w1ps + hh * 9 * OC;

    u64 a[9];
    #pragma unroll
    for (int k = 0; k < 9; k++) a[k] = 0ULL;

    #pragma unroll 4
    for (int o = 0; o < OC; o++) {
        float yo = ys[o * YSTRIDE + px];
        u64 yp = pack2(yo, yo);
        #pragma unroll
        for (int k = 0; k < 9; k++) fma2(a[k], wrow[k * OC + o], yp);
    }

    // BN + ReLU + softmax over k for both u components
    float2 e[9];
    float mx0 = -1e30f, mx1 = -1e30f;
    #pragma unroll
    for (int k = 0; k < 9; k++) {
        int p0c = k * 4 + hh, p1c = p0c + 2;
        float2 v = unpack2(a[k]);
        v.x = fmaxf(fmaf(v.x, g_A1[p0c], g_B1[p0c]), 0.f);
        v.y = fmaxf(fmaf(v.y, g_A1[p1c], g_B1[p1c]), 0.f);
        e[k] = v;
        mx0 = fmaxf(mx0, v.x); mx1 = fmaxf(mx1, v.y);
    }
    float s0 = 0.f, s1 = 0.f;
    #pragma unroll
    for (int k = 0; k < 9; k++) {
        e[k].x = __expf(e[k].x - mx0); s0 += e[k].x;
        e[k].y = __expf(e[k].y - mx1); s1 += e[k].y;
    }
    float i0 = 1.f / s0, i1 = 1.f / s1;
    __syncthreads();   // all reads of w0s region done; safe to alias wts_s
    #pragma unroll
    for (int k = 0; k < 9; k++) {
        wts_s[px * 37 + k * 4 + hh]     = e[k].x * i0;
        wts_s[px * 37 + k * 4 + hh + 2] = e[k].y * i1;
    }
    __syncthreads();

    // ---- phase 4: coalesced dump to g_wts ----
    float4* gdst = (float4*)(g_wts + (size_t)(n * HW + p0) * Pp);
    for (int i4 = t; i4 < (256 * Pp) / 4; i4 += 512) {
        float4 v;
        int lin = i4 * 4;
        v.x = wts_s[(lin    ) / 36 * 37 + (lin    ) % 36];
        v.y = wts_s[(lin + 1) / 36 * 37 + (lin + 1) % 36];
        v.z = wts_s[(lin + 2) / 36 * 37 + (lin + 2) % 36];
        v.w = wts_s[(lin + 3) / 36 * 37 + (lin + 3) % 36];
        gdst[i4] = v;
    }
}

// ---------------------------------------------------------------------------
// Kernel 2: reassembly + pixelshuffle, cp.async double-buffered halo chunks.
// ---------------------------------------------------------------------------
__device__ __forceinline__ void cp_async4(u32 dst, const void* src, bool ok) {
    asm volatile("cp.async.ca.shared.global [%0], [%1], 4, %2;"
                 :: "r"(dst), "l"(src), "r"(ok ? 4 : 0));
}
__device__ __forceinline__ void cp_commit() {
    asm volatile("cp.async.commit_group;");
}
__device__ __forceinline__ void cp_wait_all() {
    asm volatile("cp.async.wait_group 0;" ::: "memory");
}

extern "C" __global__ void __launch_bounds__(256)
k_reassemble(const float* __restrict__ x, float* __restrict__ out)
{
    __shared__ float xs[2][8][10][34];

    const int tid = threadIdx.x;
    const int tx  = tid & 31;
    const int ty  = tid >> 5;
    const int w0p = blockIdx.x * 32;
    const int h0  = blockIdx.y * 8;
    const int n   = blockIdx.z >> 2;
    const int c0  = (blockIdx.z & 3) * 64;
    const int h   = h0 + ty;
    const int w   = w0p + tx;

    const float* xb = x + (size_t)n * Cc * HW;
    u32 s_base = (u32)__cvta_generic_to_shared(&xs[0][0][0][0]);

    // prefetch chunk 0
    {
        u32 sb = s_base;
        for (int e = tid; e < 8 * 10 * 34; e += 256) {
            int cl = e / 340, r = e % 340;
            int row = r / 34, col = r % 34;
            int gh = h0 - 1 + row, gw = w0p - 1 + col;
            bool ok = ((unsigned)gh < (unsigned)Hh) & ((unsigned)gw < (unsigned)Ww);
            const float* src = ok ? (xb + (size_t)(c0 + cl) * HW + gh * Ww + gw) : xb;
            cp_async4(sb + e * 4, src, ok);
        }
        cp_commit();
    }

    // load this pixel's 36 softmax weights (overlaps with prefetch)
    const float4* wp4 = (const float4*)(g_wts + (size_t)(n * HW + h * Ww + w) * Pp);
    u64 wp01[9], wp23[9];
    #pragma unroll
    for (int k = 0; k < 9; k++) {
        float4 v = __ldg(wp4 + k);
        wp01[k] = pack2(v.x, v.y);
        wp23[k] = pack2(v.z, v.w);
    }

    float* ob = out + (size_t)n * Cc * (HW * 4);

    for (int ch8 = 0; ch8 < 8; ch8++) {
        cp_wait_all();
        __syncthreads();

        if (ch8 < 7) {
            int chn = (ch8 + 1) * 8;
            u32 sb = s_base + ((ch8 + 1) & 1) * (8 * 10 * 34 * 4);
            for (int e = tid; e < 8 * 10 * 34; e += 256) {
                int cl = e / 340, r = e % 340;
                int row = r / 34, col = r % 34;
                int gh = h0 - 1 + row, gw = w0p - 1 + col;
                bool ok = ((unsigned)gh < (unsigned)Hh) & ((unsigned)gw < (unsigned)Ww);
                const float* src = ok ? (xb + (size_t)(c0 + chn + cl) * HW + gh * Ww + gw) : xb;
                cp_async4(sb + e * 4, src, ok);
            }
            cp_commit();
        }

        const int b = ch8 & 1;
        #pragma unroll
        for (int cl = 0; cl < 8; cl++) {
            int c = c0 + ch8 * 8 + cl;
            u64 a01 = 0ULL, a23 = 0ULL;
            #pragma unroll
            for (int dy = 0; dy < 3; dy++) {
                #pragma unroll
                for (int dx = 0; dx < 3; dx++) {
                    float xv = xs[b][cl][ty + dy][tx + dx];
                    u64 xp = pack2(xv, xv);
                    int k = dy * 3 + dx;
                    fma2(a01, xp, wp01[k]);
                    fma2(a23, xp, wp23[k]);
                }
            }
            float* op = ob + (size_t)c * (HW * 4) + (2 * h) * 128 + 2 * w;
            *(float2*)op         = unpack2(a01);
            *(float2*)(op + 128) = unpack2(a23);
        }
    }
}

extern "C" void kernel_launch(void* const* d_in, const int* in_sizes, int n_in,
                              void* d_out, int out_size)
{
    const float* x     = (const float*)d_in[0];
    const float* w0    = (const float*)d_in[1];
    const float* b0    = (const float*)d_in[2];
    const float* bn0_g = (const float*)d_in[3];
    const float* bn0_b = (const float*)d_in[4];
    const float* bn0_m = (const float*)d_in[5];
    const float* bn0_v = (const float*)d_in[6];
    const float* w1    = (const float*)d_in[7];
    const float* b1    = (const float*)d_in[8];
    const float* bn1_g = (const float*)d_in[9];
    const float* bn1_b = (const float*)d_in[10];
    const float* bn1_m = (const float*)d_in[11];
    const float* bn1_v = (const float*)d_in[12];
    float* out = (float*)d_out;

    k_prep<<<32, 512>>>(w0, b0, bn0_g, bn0_b, bn0_m, bn0_v,
                        w1, b1, bn1_g, bn1_b, bn1_m, bn1_v);

    cudaFuncSetAttribute(k_weights, cudaFuncAttributeMaxDynamicSharedMemorySize, SMEM1);
    dim3 g1(16, Nn);              // 256 px per block
    k_weights<<<g1, 512, SMEM1>>>(x);

    dim3 g2(2, 8, Nn * 4);
    k_reassemble<<<g2, 256>>>(x, out);
}

// round 3
// speedup vs baseline: 1.6232x; 1.2455x over previous
#include <cuda_runtime.h>

#define EPS 1e-5f

#define Nn 8
#define Cc 256
#define Hh 64
#define Ww 64
#define HW 4096
#define OC 64
#define Pp 36

typedef unsigned long long u64;
typedef unsigned int u32;

// softmax weights scratch: [n][px][36]
__device__ float g_wts[(size_t)Nn * HW * Pp];

__device__ __forceinline__ u64 pack2(float x, float y) {
    u64 r; asm("mov.b64 %0, {%1,%2};" : "=l"(r) : "f"(x), "f"(y)); return r;
}
__device__ __forceinline__ void fma2(u64 &d, u64 a, u64 b) {
    asm("fma.rn.f32x2 %0, %1, %2, %0;" : "+l"(d) : "l"(a), "l"(b));
}
__device__ __forceinline__ float2 unpack2(u64 v) {
    float2 r; asm("mov.b64 {%0,%1}, %2;" : "=f"(r.x), "=f"(r.y) : "l"(v)); return r;
}

// ---------------------------------------------------------------------------
// Kernel 1: per-pixel weight computation. 512 threads, 256 px per block.
// smem (bytes):
//   [0      , 65536 )  w0s [256c][64oc]         (alias: wts_s [256px][37] phase 4)
//   [65536  , 98304 )  xs  [2][16k][256px]
//   [98304  , 164096)  ys  [64oc][257px]
//   [164096 , 173312)  w1p [2][9][64] u64
//   [173312 , 174144)  A0[64] B0[64] A1[36+pad] B1[36+pad]
// ---------------------------------------------------------------------------
#define OFF_W0  0
#define OFF_XS  65536
#define OFF_YS  98304
#define OFF_W1P 164096
#define OFF_CST 173312
#define SMEM1   174144
#define YSTRIDE 257

extern "C" __global__ void __launch_bounds__(512, 1)
k_weights(const float* __restrict__ x,
          const float* __restrict__ w0, const float* __restrict__ b0,
          const float* __restrict__ bn0_g, const float* __restrict__ bn0_b,
          const float* __restrict__ bn0_m, const float* __restrict__ bn0_v,
          const float* __restrict__ w1, const float* __restrict__ b1,
          const float* __restrict__ bn1_g, const float* __restrict__ bn1_b,
          const float* __restrict__ bn1_m, const float* __restrict__ bn1_v)
{
    extern __shared__ char smem[];
    float* w0s   = (float*)(smem + OFF_W0);
    float* ys    = (float*)(smem + OFF_YS);
    u64*   w1ps  = (u64*)  (smem + OFF_W1P);
    float* cA0   = (float*)(smem + OFF_CST);
    float* cB0   = cA0 + 64;
    float* cA1   = cB0 + 64;
    float* cB1   = cA1 + 40;
    float* wts_s = (float*)(smem + OFF_W0);   // phase-4 alias

    const int t  = threadIdx.x;
    const int n  = blockIdx.y;
    const int p0 = blockIdx.x * 256;

    const float* xn = x + (size_t)n * Cc * HW + p0;

    // prefetch x chunk 0 into registers (c = warp, px = lane*8)
    const int lc = t >> 5;
    const int lp = (t & 31) * 8;
    float4 ra = *(const float4*)(xn + (size_t)lc * HW + lp);
    float4 rb = *(const float4*)(xn + (size_t)lc * HW + lp + 4);

    // ---- fold BN constants (was k_prep) ----
    if (t < 64) {
        float A = bn0_g[t] * rsqrtf(bn0_v[t] + EPS);
        cA0[t] = A;
        cB0[t] = (b0[t] - bn0_m[t]) * A + bn0_b[t];
    } else if (t >= 64 && t < 64 + Pp) {
        int i = t - 64;
        float A = bn1_g[i] * rsqrtf(bn1_v[i] + EPS);
        cA1[i] = A;
        cB1[i] = (b1[i] - bn1_m[i]) * A + bn1_b[i];
    }

    // ---- stage w1 packed pairs: w1ps[h][k][o] = (w1[4k+h][o], w1[4k+h+2][o]) ----
    for (int i = t; i < 2 * 9 * OC; i += 512) {
        int h = i / (9 * OC), k = (i / OC) % 9, o = i % OC;
        w1ps[i] = pack2(w1[(4 * k + h) * OC + o], w1[(4 * k + h + 2) * OC + o]);
    }

    // ---- stage w0 transposed: w0s[c][oc]; lane==oc -> conflict-free STS ----
    {
        const int oc = t & 63;          // 64 oc
        const int cg = t >> 6;          // 8 c-groups of 32
        const float* src = w0 + oc * Cc + cg * 32;
        #pragma unroll
        for (int j4 = 0; j4 < 8; j4++) {
            float4 v = *(const float4*)(src + j4 * 4);
            w0s[(cg * 32 + j4 * 4 + 0) * 64 + oc] = v.x;
            w0s[(cg * 32 + j4 * 4 + 1) * 64 + oc] = v.y;
            w0s[(cg * 32 + j4 * 4 + 2) * 64 + oc] = v.z;
            w0s[(cg * 32 + j4 * 4 + 3) * 64 + oc] = v.w;
        }
    }

    // ---- phase 2: GEMM 64oc x 256px, broadcast-weight mapping ----
    // warp: ocg = warp&3 (16 oc), pxg = warp>>2 (64 px); lane: 2 px
    const int warp = t >> 5, lane = t & 31;
    const int ocb  = (warp & 3) * 16;
    const int pxb  = (warp >> 2) * 64 + lane * 2;

    u64 acc[8][2];
    #pragma unroll
    for (int i = 0; i < 8; i++) { acc[i][0] = 0ULL; acc[i][1] = 0ULL; }

    for (int kc = 0; kc < 16; kc++) {
        float* xbuf = (float*)(smem + OFF_XS + (kc & 1) * 16384);
        *(float4*)(xbuf + lc * 256 + lp)     = ra;
        *(float4*)(xbuf + lc * 256 + lp + 4) = rb;
        __syncthreads();
        if (kc < 15) {
            const float* src = xn + (size_t)((kc + 1) * 16 + lc) * HW + lp;
            ra = *(const float4*)src;
            rb = *(const float4*)(src + 4);
        }
        const float* wbase = w0s + kc * 16 * 64 + ocb;
        const float* xbase = xbuf + pxb;
        #pragma unroll
        for (int kk = 0; kk < 16; kk++) {
            const ulonglong2* wr = (const ulonglong2*)(wbase + kk * 64);
            ulonglong2 wa = wr[0];   // (oc0,oc1)(oc2,oc3)
            ulonglong2 wb = wr[1];
            ulonglong2 wc = wr[2];
            ulonglong2 wd = wr[3];
            float2 xv = *(const float2*)(xbase + kk * 256);
            u64 x0 = pack2(xv.x, xv.x);
            u64 x1 = pack2(xv.y, xv.y);
            fma2(acc[0][0], wa.x, x0); fma2(acc[0][1], wa.x, x1);
            fma2(acc[1][0], wa.y, x0); fma2(acc[1][1], wa.y, x1);
            fma2(acc[2][0], wb.x, x0); fma2(acc[2][1], wb.x, x1);
            fma2(acc[3][0], wb.y, x0); fma2(acc[3][1], wb.y, x1);
            fma2(acc[4][0], wc.x, x0); fma2(acc[4][1], wc.x, x1);
            fma2(acc[5][0], wc.y, x0); fma2(acc[5][1], wc.y, x1);
            fma2(acc[6][0], wd.x, x0); fma2(acc[6][1], wd.x, x1);
            fma2(acc[7][0], wd.y, x0); fma2(acc[7][1], wd.y, x1);
        }
    }

    // ---- epilogue: BN + ReLU -> ys ----
    #pragma unroll
    for (int i = 0; i < 8; i++) {
        int oc0 = ocb + 2 * i, oc1 = oc0 + 1;
        float Aa = cA0[oc0], Ba = cB0[oc0];
        float Ab = cA0[oc1], Bb = cB0[oc1];
        #pragma unroll
        for (int j = 0; j < 2; j++) {
            float2 v = unpack2(acc[i][j]);
            ys[oc0 * YSTRIDE + pxb + j] = fmaxf(fmaf(v.x, Aa, Ba), 0.f);
            ys[oc1 * YSTRIDE + pxb + j] = fmaxf(fmaf(v.y, Ab, Bb), 0.f);
        }
    }
    __syncthreads();

    // ---- phase 3: encoder + BN + ReLU + softmax over k ----
    const int px = t & 255;
    const int hh = t >> 8;          // 0 -> u {0,2}, 1 -> u {1,3}
    const u64* wrow = w1ps + hh * 9 * OC;

    u64 a[9];
    #pragma unroll
    for (int k = 0; k < 9; k++) a[k] = 0ULL;

    #pragma unroll 4
    for (int o = 0; o < OC; o++) {
        float yo = ys[o * YSTRIDE + px];
        u64 yp = pack2(yo, yo);
        #pragma unroll
        for (int k = 0; k < 9; k++) fma2(a[k], wrow[k * OC + o], yp);
    }

    float2 e[9];
    float mx0 = -1e30f, mx1 = -1e30f;
    #pragma unroll
    for (int k = 0; k < 9; k++) {
        int c0 = k * 4 + hh, c1 = c0 + 2;
        float2 v = unpack2(a[k]);
        v.x = fmaxf(fmaf(v.x, cA1[c0], cB1[c0]), 0.f);
        v.y = fmaxf(fmaf(v.y, cA1[c1], cB1[c1]), 0.f);
        e[k] = v;
        mx0 = fmaxf(mx0, v.x); mx1 = fmaxf(mx1, v.y);
    }
    float s0 = 0.f, s1 = 0.f;
    #pragma unroll
    for (int k = 0; k < 9; k++) {
        e[k].x = __expf(e[k].x - mx0); s0 += e[k].x;
        e[k].y = __expf(e[k].y - mx1); s1 += e[k].y;
    }
    float i0 = 1.f / s0, i1 = 1.f / s1;
    __syncthreads();   // GEMM reads of w0s done everywhere -> safe to alias
    #pragma unroll
    for (int k = 0; k < 9; k++) {
        wts_s[px * 37 + k * 4 + hh]     = e[k].x * i0;
        wts_s[px * 37 + k * 4 + hh + 2] = e[k].y * i1;
    }
    __syncthreads();

    // ---- phase 4: coalesced dump to g_wts ----
    float4* gdst = (float4*)(g_wts + (size_t)(n * HW + p0) * Pp);
    for (int i4 = t; i4 < (256 * Pp) / 4; i4 += 512) {
        float4 v;
        int lin = i4 * 4;
        v.x = wts_s[(lin    ) / 36 * 37 + (lin    ) % 36];
        v.y = wts_s[(lin + 1) / 36 * 37 + (lin + 1) % 36];
        v.z = wts_s[(lin + 2) / 36 * 37 + (lin + 2) % 36];
        v.w = wts_s[(lin + 3) / 36 * 37 + (lin + 3) % 36];
        gdst[i4] = v;
    }
}

// ---------------------------------------------------------------------------
// Kernel 2: reassembly + pixelshuffle. 32 channels/block, cp.async pipeline.
// ---------------------------------------------------------------------------
__device__ __forceinline__ void cp_async4(u32 dst, const void* src, bool ok) {
    asm volatile("cp.async.ca.shared.global [%0], [%1], 4, %2;"
                 :: "r"(dst), "l"(src), "r"(ok ? 4 : 0));
}
__device__ __forceinline__ void cp_commit() {
    asm volatile("cp.async.commit_group;");
}
__device__ __forceinline__ void cp_wait_all() {
    asm volatile("cp.async.wait_group 0;" ::: "memory");
}
__device__ __forceinline__ void stcs2(float* p, float2 v) {
    asm volatile("st.global.cs.v2.f32 [%0], {%1,%2};" :: "l"(p), "f"(v.x), "f"(v.y));
}

extern "C" __global__ void __launch_bounds__(256)
k_reassemble(const float* __restrict__ x, float* __restrict__ out)
{
    __shared__ float xs[2][8][10][34];

    const int tid = threadIdx.x;
    const int tx  = tid & 31;
    const int ty  = tid >> 5;
    const int w0p = blockIdx.x * 32;
    const int h0  = blockIdx.y * 8;
    const int n   = blockIdx.z >> 3;
    const int c0  = (blockIdx.z & 7) * 32;
    const int h   = h0 + ty;
    const int w   = w0p + tx;

    const float* xb = x + (size_t)n * Cc * HW;
    u32 s_base = (u32)__cvta_generic_to_shared(&xs[0][0][0][0]);

    // prefetch chunk 0
    for (int e = tid; e < 8 * 10 * 34; e += 256) {
        int cl = e / 340, r = e % 340;
        int row = r / 34, col = r % 34;
        int gh = h0 - 1 + row, gw = w0p - 1 + col;
        bool ok = ((unsigned)gh < (unsigned)Hh) & ((unsigned)gw < (unsigned)Ww);
        const float* src = ok ? (xb + (size_t)(c0 + cl) * HW + gh * Ww + gw) : xb;
        cp_async4(s_base + e * 4, src, ok);
    }
    cp_commit();

    // this pixel's 36 softmax weights (overlaps with prefetch)
    const float4* wp4 = (const float4*)(g_wts + (size_t)(n * HW + h * Ww + w) * Pp);
    u64 wp01[9], wp23[9];
    #pragma unroll
    for (int k = 0; k < 9; k++) {
        float4 v = __ldg(wp4 + k);
        wp01[k] = pack2(v.x, v.y);
        wp23[k] = pack2(v.z, v.w);
    }

    float* ob = out + (size_t)n * Cc * (HW * 4);

    for (int ch8 = 0; ch8 < 4; ch8++) {
        cp_wait_all();
        __syncthreads();

        if (ch8 < 3) {
            int chn = (ch8 + 1) * 8;
            u32 sb = s_base + ((ch8 + 1) & 1) * (8 * 10 * 34 * 4);
            for (int e = tid; e < 8 * 10 * 34; e += 256) {
                int cl = e / 340, r = e % 340;
                int row = r / 34, col = r % 34;
                int gh = h0 - 1 + row, gw = w0p - 1 + col;
                bool ok = ((unsigned)gh < (unsigned)Hh) & ((unsigned)gw < (unsigned)Ww);
                const float* src = ok ? (xb + (size_t)(c0 + chn + cl) * HW + gh * Ww + gw) : xb;
                cp_async4(sb + e * 4, src, ok);
            }
            cp_commit();
        }

        const int b = ch8 & 1;
        #pragma unroll
        for (int cl = 0; cl < 8; cl++) {
            int c = c0 + ch8 * 8 + cl;
            u64 a01 = 0ULL, a23 = 0ULL;
            #pragma unroll
            for (int dy = 0; dy < 3; dy++) {
                #pragma unroll
                for (int dx = 0; dx < 3; dx++) {
                    float xv = xs[b][cl][ty + dy][tx + dx];
                    u64 xp = pack2(xv, xv);
                    int k = dy * 3 + dx;
                    fma2(a01, xp, wp01[k]);
                    fma2(a23, xp, wp23[k]);
                }
            }
            float* op = ob + (size_t)c * (HW * 4) + (2 * h) * 128 + 2 * w;
            stcs2(op,       unpack2(a01));
            stcs2(op + 128, unpack2(a23));
        }
    }
}

extern "C" void kernel_launch(void* const* d_in, const int* in_sizes, int n_in,
                              void* d_out, int out_size)
{
    const float* x     = (const float*)d_in[0];
    const float* w0    = (const float*)d_in[1];
    const float* b0    = (const float*)d_in[2];
    const float* bn0_g = (const float*)d_in[3];
    const float* bn0_b = (const float*)d_in[4];
    const float* bn0_m = (const float*)d_in[5];
    const float* bn0_v = (const float*)d_in[6];
    const float* w1    = (const float*)d_in[7];
    const float* b1    = (const float*)d_in[8];
    const float* bn1_g = (const float*)d_in[9];
    const float* bn1_b = (const float*)d_in[10];
    const float* bn1_m = (const float*)d_in[11];
    const float* bn1_v = (const float*)d_in[12];
    float* out = (float*)d_out;

    cudaFuncSetAttribute(k_weights, cudaFuncAttributeMaxDynamicSharedMemorySize, SMEM1);
    dim3 g1(16, Nn);
    k_weights<<<g1, 512, SMEM1>>>(x, w0, b0, bn0_g, bn0_b, bn0_m, bn0_v,
                                  w1, b1, bn1_g, bn1_b, bn1_m, bn1_v);

    dim3 g2(2, 8, Nn * 8);
    k_reassemble<<<g2, 256>>>(x, out);
}

// round 4
// speedup vs baseline: 1.6661x; 1.0265x over previous
#include <cuda_runtime.h>

#define EPS 1e-5f

#define Nn 8
#define Cc 256
#define Hh 64
#define Ww 64
#define HW 4096
#define OC 64
#define Pp 36

typedef unsigned long long u64;
typedef unsigned int u32;

// softmax weights scratch: [n][px][36]
__device__ float g_wts[(size_t)Nn * HW * Pp];

__device__ __forceinline__ u64 pack2(float x, float y) {
    u64 r; asm("mov.b64 %0, {%1,%2};" : "=l"(r) : "f"(x), "f"(y)); return r;
}
__device__ __forceinline__ void fma2(u64 &d, u64 a, u64 b) {
    asm("fma.rn.f32x2 %0, %1, %2, %0;" : "+l"(d) : "l"(a), "l"(b));
}
__device__ __forceinline__ float2 unpack2(u64 v) {
    float2 r; asm("mov.b64 {%0,%1}, %2;" : "=f"(r.x), "=f"(r.y) : "l"(v)); return r;
}

// ---------------------------------------------------------------------------
// Kernel 1: per-pixel weight computation.
// 256 threads, 128 px per block, 256 blocks -> 2 CTAs/SM.
// smem (bytes):
//   [0     , 65536)  w0s [256c][64oc]
//                    alias after GEMM: ys [64][129] @0 (33024B),
//                                      wts_s [128][37] @33024 (18944B)
//   [65536 , 81920)  xs [2][16k][128px]
//   [81920 , 91136)  w1p [2][9][64] u64
//   [91136 , 91968)  A0[64] B0[64] A1[40] B1[40]
// ---------------------------------------------------------------------------
#define OFF_XS   65536
#define OFF_W1P  81920
#define OFF_CST  91136
#define SMEM1    91968
#define OFF_YS_A 0
#define OFF_WS_A 33024
#define YSTRIDE  129

extern "C" __global__ void __launch_bounds__(256, 2)
k_weights(const float* __restrict__ x,
          const float* __restrict__ w0, const float* __restrict__ b0,
          const float* __restrict__ bn0_g, const float* __restrict__ bn0_b,
          const float* __restrict__ bn0_m, const float* __restrict__ bn0_v,
          const float* __restrict__ w1, const float* __restrict__ b1,
          const float* __restrict__ bn1_g, const float* __restrict__ bn1_b,
          const float* __restrict__ bn1_m, const float* __restrict__ bn1_v)
{
    extern __shared__ char smem[];
    float* w0s   = (float*)smem;
    float* ys    = (float*)(smem + OFF_YS_A);
    float* wts_s = (float*)(smem + OFF_WS_A);
    u64*   w1ps  = (u64*)  (smem + OFF_W1P);
    float* cA0   = (float*)(smem + OFF_CST);
    float* cB0   = cA0 + 64;
    float* cA1   = cB0 + 64;
    float* cB1   = cA1 + 40;

    const int t  = threadIdx.x;
    const int n  = blockIdx.y;
    const int p0 = blockIdx.x * 128;

    const float* xn = x + (size_t)n * Cc * HW + p0;

    // prefetch x chunk 0: c-row = t/16, px = (t%16)*8
    const int lc = t >> 4;
    const int lp = (t & 15) * 8;
    float4 ra = *(const float4*)(xn + (size_t)lc * HW + lp);
    float4 rb = *(const float4*)(xn + (size_t)lc * HW + lp + 4);

    // fold BN constants
    if (t < 64) {
        float A = bn0_g[t] * rsqrtf(bn0_v[t] + EPS);
        cA0[t] = A;
        cB0[t] = (b0[t] - bn0_m[t]) * A + bn0_b[t];
    } else if (t < 64 + Pp) {
        int i = t - 64;
        float A = bn1_g[i] * rsqrtf(bn1_v[i] + EPS);
        cA1[i] = A;
        cB1[i] = (b1[i] - bn1_m[i]) * A + bn1_b[i];
    }

    // stage w1 packed pairs: w1ps[h][k][o] = (w1[4k+h][o], w1[4k+h+2][o])
    for (int i = t; i < 2 * 9 * OC; i += 256) {
        int hq = i / (9 * OC), k = (i / OC) % 9, o = i % OC;
        w1ps[i] = pack2(w1[(4 * k + hq) * OC + o], w1[(4 * k + hq + 2) * OC + o]);
    }

    // stage w0 transposed: w0s[c][oc]; lane==oc -> conflict-free STS
    {
        const int oc = t & 63;
        const int cg = t >> 6;          // 4 c-groups of 64
        const float* src = w0 + oc * Cc + cg * 64;
        #pragma unroll
        for (int j4 = 0; j4 < 16; j4++) {
            float4 v = *(const float4*)(src + j4 * 4);
            w0s[(cg * 64 + j4 * 4 + 0) * 64 + oc] = v.x;
            w0s[(cg * 64 + j4 * 4 + 1) * 64 + oc] = v.y;
            w0s[(cg * 64 + j4 * 4 + 2) * 64 + oc] = v.z;
            w0s[(cg * 64 + j4 * 4 + 3) * 64 + oc] = v.w;
        }
    }

    // ---- phase 2: GEMM 64oc x 128px ----
    // warp: ocg = warp&3 (16 oc), pxg = warp>>2 (64 px); lane: 2 px
    const int warp = t >> 5, lane = t & 31;
    const int ocb  = (warp & 3) * 16;
    const int pxb  = (warp >> 2) * 64 + lane * 2;

    u64 acc[8][2];
    #pragma unroll
    for (int i = 0; i < 8; i++) { acc[i][0] = 0ULL; acc[i][1] = 0ULL; }

    for (int kc = 0; kc < 16; kc++) {
        float* xbuf = (float*)(smem + OFF_XS + (kc & 1) * 8192);
        *(float4*)(xbuf + lc * 128 + lp)     = ra;
        *(float4*)(xbuf + lc * 128 + lp + 4) = rb;
        __syncthreads();
        if (kc < 15) {
            const float* src = xn + (size_t)((kc + 1) * 16 + lc) * HW + lp;
            ra = *(const float4*)src;
            rb = *(const float4*)(src + 4);
        }
        const float* wbase = w0s + kc * 16 * 64 + ocb;
        const float* xbase = xbuf + pxb;
        #pragma unroll
        for (int kk = 0; kk < 16; kk++) {
            const ulonglong2* wr = (const ulonglong2*)(wbase + kk * 64);
            ulonglong2 wa = wr[0];
            ulonglong2 wb = wr[1];
            ulonglong2 wc = wr[2];
            ulonglong2 wd = wr[3];
            float2 xv = *(const float2*)(xbase + kk * 128);
            u64 x0 = pack2(xv.x, xv.x);
            u64 x1 = pack2(xv.y, xv.y);
            fma2(acc[0][0], wa.x, x0); fma2(acc[0][1], wa.x, x1);
            fma2(acc[1][0], wa.y, x0); fma2(acc[1][1], wa.y, x1);
            fma2(acc[2][0], wb.x, x0); fma2(acc[2][1], wb.x, x1);
            fma2(acc[3][0], wb.y, x0); fma2(acc[3][1], wb.y, x1);
            fma2(acc[4][0], wc.x, x0); fma2(acc[4][1], wc.x, x1);
            fma2(acc[5][0], wc.y, x0); fma2(acc[5][1], wc.y, x1);
            fma2(acc[6][0], wd.x, x0); fma2(acc[6][1], wd.x, x1);
            fma2(acc[7][0], wd.y, x0); fma2(acc[7][1], wd.y, x1);
        }
    }
    __syncthreads();   // all w0s reads done -> safe to alias ys over it

    // ---- epilogue: BN + ReLU -> ys ----
    #pragma unroll
    for (int i = 0; i < 8; i++) {
        int oc0 = ocb + 2 * i, oc1 = oc0 + 1;
        float Aa = cA0[oc0], Ba = cB0[oc0];
        float Ab = cA0[oc1], Bb = cB0[oc1];
        #pragma unroll
        for (int j = 0; j < 2; j++) {
            float2 v = unpack2(acc[i][j]);
            ys[oc0 * YSTRIDE + pxb + j] = fmaxf(fmaf(v.x, Aa, Ba), 0.f);
            ys[oc1 * YSTRIDE + pxb + j] = fmaxf(fmaf(v.y, Ab, Bb), 0.f);
        }
    }
    __syncthreads();

    // ---- phase 3: encoder + BN + ReLU + softmax over k ----
    const int px = t & 127;
    const int hh = t >> 7;          // 0 -> u {0,2}, 1 -> u {1,3}
    const u64* wrow = w1ps + hh * 9 * OC;

    u64 a[9];
    #pragma unroll
    for (int k = 0; k < 9; k++) a[k] = 0ULL;

    #pragma unroll 4
    for (int o = 0; o < OC; o++) {
        float yo = ys[o * YSTRIDE + px];
        u64 yp = pack2(yo, yo);
        #pragma unroll
        for (int k = 0; k < 9; k++) fma2(a[k], wrow[k * OC + o], yp);
    }

    float2 e[9];
    float mx0 = -1e30f, mx1 = -1e30f;
    #pragma unroll
    for (int k = 0; k < 9; k++) {
        int c0 = k * 4 + hh, c1 = c0 + 2;
        float2 v = unpack2(a[k]);
        v.x = fmaxf(fmaf(v.x, cA1[c0], cB1[c0]), 0.f);
        v.y = fmaxf(fmaf(v.y, cA1[c1], cB1[c1]), 0.f);
        e[k] = v;
        mx0 = fmaxf(mx0, v.x); mx1 = fmaxf(mx1, v.y);
    }
    float s0 = 0.f, s1 = 0.f;
    #pragma unroll
    for (int k = 0; k < 9; k++) {
        e[k].x = __expf(e[k].x - mx0); s0 += e[k].x;
        e[k].y = __expf(e[k].y - mx1); s1 += e[k].y;
    }
    float i0 = 1.f / s0, i1 = 1.f / s1;
    #pragma unroll
    for (int k = 0; k < 9; k++) {
        wts_s[px * 37 + k * 4 + hh]     = e[k].x * i0;
        wts_s[px * 37 + k * 4 + hh + 2] = e[k].y * i1;
    }
    __syncthreads();

    // ---- phase 4: coalesced dump to g_wts ----
    float4* gdst = (float4*)(g_wts + (size_t)(n * HW + p0) * Pp);
    for (int i4 = t; i4 < (128 * Pp) / 4; i4 += 256) {
        float4 v;
        int lin = i4 * 4;
        v.x = wts_s[(lin    ) / 36 * 37 + (lin    ) % 36];
        v.y = wts_s[(lin + 1) / 36 * 37 + (lin + 1) % 36];
        v.z = wts_s[(lin + 2) / 36 * 37 + (lin + 2) % 36];
        v.w = wts_s[(lin + 3) / 36 * 37 + (lin + 3) % 36];
        gdst[i4] = v;
    }
}

// ---------------------------------------------------------------------------
// Kernel 2: reassembly + pixelshuffle. Geometry fully hoisted; per chunk the
// only address math is a channel-base pointer bump.
// ---------------------------------------------------------------------------
__device__ __forceinline__ void cp_async4(u32 dst, const void* src, bool ok) {
    asm volatile("cp.async.ca.shared.global [%0], [%1], 4, %2;"
                 :: "r"(dst), "l"(src), "r"(ok ? 4 : 0));
}
__device__ __forceinline__ void cp_commit() {
    asm volatile("cp.async.commit_group;");
}
__device__ __forceinline__ void cp_wait_all() {
    asm volatile("cp.async.wait_group 0;" ::: "memory");
}
__device__ __forceinline__ void stcs2(float* p, float2 v) {
    asm volatile("st.global.cs.v2.f32 [%0], {%1,%2};" :: "l"(p), "f"(v.x), "f"(v.y));
}

#define CHUNK_B (8 * 10 * 34 * 4)   // bytes per halo chunk buffer

extern "C" __global__ void __launch_bounds__(256)
k_reassemble(const float* __restrict__ x, float* __restrict__ out)
{
    __shared__ float xs[2][8][10][34];

    const int tid = threadIdx.x;
    const int tx   = tid & 31;
    const int warp = tid >> 5;          // loader: warp = channel-in-chunk
    const int w0p = blockIdx.x * 32;
    const int h0  = blockIdx.y * 8;
    const int n   = blockIdx.z >> 3;
    const int c0  = (blockIdx.z & 7) * 32;
    const int h   = h0 + (tid >> 5);
    const int w   = w0p + tx;

    const float* xb = x + (size_t)n * Cc * HW;
    u32 s_base = (u32)__cvta_generic_to_shared(&xs[0][0][0][0]);

    // ---- hoisted halo geometry (loader view): warp = cl, lane covers
    //      col = tx (all lanes) and col = tx+32 (lanes 0,1 only) ----
    const bool col1ok = (w0p + tx - 1) >= 0 && (w0p + tx - 1) < Ww;            // gw = w0p-1+tx
    const bool do2    = (tx < 2);
    const bool col2ok = do2 && ((w0p - 1 + tx + 32) < Ww);                     // gw2
    // per-row validity: gh = h0-1+r
    // base global pointer for (row 0, col tx):
    const float* gBase = xb + (size_t)(c0 + warp) * HW + (h0 - 1) * Ww + (w0p - 1 + tx);
    const u32    sRow0 = s_base + (warp * 10 * 34 + tx) * 4;

    // ---- prefetch chunk 0 ----
    {
        const float* g = gBase;
        u32 s = sRow0;
        #pragma unroll
        for (int r = 0; r < 10; r++) {
            bool rok = ((unsigned)(h0 - 1 + r) < (unsigned)Hh);
            cp_async4(s,      rok && col1ok ? g      : xb, rok && col1ok);
            if (do2)
                cp_async4(s + 128, rok && col2ok ? g + 32 : xb, rok && col2ok);
            g += Ww; s += 136;
        }
        cp_commit();
    }

    // this pixel's 36 softmax weights (overlaps with prefetch)
    const float4* wp4 = (const float4*)(g_wts + (size_t)(n * HW + h * Ww + w) * Pp);
    u64 wp01[9], wp23[9];
    #pragma unroll
    for (int k = 0; k < 9; k++) {
        float4 v = __ldg(wp4 + k);
        wp01[k] = pack2(v.x, v.y);
        wp23[k] = pack2(v.z, v.w);
    }

    const int ty = tid >> 5;
    float* op = out + (size_t)n * Cc * (HW * 4)
                    + (size_t)c0 * (HW * 4) + (2 * h) * 128 + 2 * w;

    for (int ch8 = 0; ch8 < 4; ch8++) {
        cp_wait_all();
        __syncthreads();

        if (ch8 < 3) {
            const float* g = gBase + (size_t)(ch8 + 1) * 8 * HW;
            u32 s = sRow0 + ((ch8 + 1) & 1) * CHUNK_B;
            #pragma unroll
            for (int r = 0; r < 10; r++) {
                bool rok = ((unsigned)(h0 - 1 + r) < (unsigned)Hh);
                cp_async4(s,      rok && col1ok ? g      : xb, rok && col1ok);
                if (do2)
                    cp_async4(s + 128, rok && col2ok ? g + 32 : xb, rok && col2ok);
                g += Ww; s += 136;
            }
            cp_commit();
        }

        const int b = ch8 & 1;
        #pragma unroll
        for (int cl = 0; cl < 8; cl++) {
            u64 a01 = 0ULL, a23 = 0ULL;
            #pragma unroll
            for (int dy = 0; dy < 3; dy++) {
                #pragma unroll
                for (int dx = 0; dx < 3; dx++) {
                    float xv = xs[b][cl][ty + dy][tx + dx];
                    u64 xp = pack2(xv, xv);
                    int k = dy * 3 + dx;
                    fma2(a01, xp, wp01[k]);
                    fma2(a23, xp, wp23[k]);
                }
            }
            stcs2(op,       unpack2(a01));
            stcs2(op + 128, unpack2(a23));
            op += HW * 4;       // next channel
        }
    }
}

extern "C" void kernel_launch(void* const* d_in, const int* in_sizes, int n_in,
                              void* d_out, int out_size)
{
    const float* x     = (const float*)d_in[0];
    const float* w0    = (const float*)d_in[1];
    const float* b0    = (const float*)d_in[2];
    const float* bn0_g = (const float*)d_in[3];
    const float* bn0_b = (const float*)d_in[4];
    const float* bn0_m = (const float*)d_in[5];
    const float* bn0_v = (const float*)d_in[6];
    const float* w1    = (const float*)d_in[7];
    const float* b1    = (const float*)d_in[8];
    const float* bn1_g = (const float*)d_in[9];
    const float* bn1_b = (const float*)d_in[10];
    const float* bn1_m = (const float*)d_in[11];
    const float* bn1_v = (const float*)d_in[12];
    float* out = (float*)d_out;

    cudaFuncSetAttribute(k_weights, cudaFuncAttributeMaxDynamicSharedMemorySize, SMEM1);
    dim3 g1(32, Nn);              // 128 px per block, 256 blocks
    k_weights<<<g1, 256, SMEM1>>>(x, w0, b0, bn0_g, bn0_b, bn0_m, bn0_v,
                                  w1, b1, bn1_g, bn1_b, bn1_m, bn1_v);

    dim3 g2(2, 8, Nn * 8);
    k_reassemble<<<g2, 256>>>(x, out);
}

// round 6
// speedup vs baseline: 2.1416x; 1.2854x over previous
#include <cuda_runtime.h>
#include <cstdint>

#define EPS 1e-5f
#define Nn 8
#define Cc 256
#define Hh 64
#define Ww 64
#define HW 4096
#define OC 64
#define Pp 36

typedef unsigned long long u64;
typedef unsigned int u32;
typedef unsigned short u16;

// softmax weights scratch: [n][px][36]
__device__ float g_wts[(size_t)Nn * HW * Pp];

__device__ __forceinline__ u64 pack2(float x, float y) {
    u64 r; asm("mov.b64 %0, {%1,%2};" : "=l"(r) : "f"(x), "f"(y)); return r;
}
__device__ __forceinline__ void fma2(u64 &d, u64 a, u64 b) {
    asm("fma.rn.f32x2 %0, %1, %2, %0;" : "+l"(d) : "l"(a), "l"(b));
}
__device__ __forceinline__ float2 unpack2(u64 v) {
    float2 r; asm("mov.b64 {%0,%1}, %2;" : "=f"(r.x), "=f"(r.y) : "l"(v)); return r;
}
__device__ __forceinline__ u32 smem_u32(const void* p) {
    u32 a;
    asm("{ .reg .u64 t; cvta.to.shared.u64 t, %1; cvt.u32.u64 %0, t; }" : "=r"(a) : "l"(p));
    return a;
}
__device__ __forceinline__ void ldsm4(u32& r0, u32& r1, u32& r2, u32& r3, u32 addr) {
    asm volatile("ldmatrix.sync.aligned.m8n8.x4.shared.b16 {%0,%1,%2,%3}, [%4];"
                 : "=r"(r0), "=r"(r1), "=r"(r2), "=r"(r3) : "r"(addr));
}
__device__ __forceinline__ void ldsm4t(u32& r0, u32& r1, u32& r2, u32& r3, u32 addr) {
    asm volatile("ldmatrix.sync.aligned.m8n8.x4.trans.shared.b16 {%0,%1,%2,%3}, [%4];"
                 : "=r"(r0), "=r"(r1), "=r"(r2), "=r"(r3) : "r"(addr));
}
__device__ __forceinline__ void mma16816(float* c, u32 a0, u32 a1, u32 a2, u32 a3,
                                          u32 b0, u32 b1) {
    asm volatile("mma.sync.aligned.m16n8k16.row.col.f32.bf16.bf16.f32 "
                 "{%0,%1,%2,%3}, {%4,%5,%6,%7}, {%8,%9}, {%0,%1,%2,%3};"
                 : "+f"(c[0]), "+f"(c[1]), "+f"(c[2]), "+f"(c[3])
                 : "r"(a0), "r"(a1), "r"(a2), "r"(a3), "r"(b0), "r"(b1));
}
// split f32 pair -> bf16x2 hi + lo
__device__ __forceinline__ void split2(float vx, float vy, u32& hi, u32& lo) {
    u32 h; asm("cvt.rn.bf16x2.f32 %0, %1, %2;" : "=r"(h) : "f"(vy), "f"(vx));
    float hx = __uint_as_float(h << 16);
    float hy = __uint_as_float(h & 0xffff0000u);
    u32 l; asm("cvt.rn.bf16x2.f32 %0, %1, %2;" : "=r"(l) : "f"(vy - hy), "f"(vx - hx));
    hi = h; lo = l;
}

// ---------------------------------------------------------------------------
// Kernel 1: per-pixel weight computation. 256 threads, 128 px, 256 blocks.
// Layer0 GEMM on tensor cores (mma.sync bf16 hi/lo split), encoder fp32.
// smem (bytes):
//   [0      , 34816 )  As_hi [128 k][272B rows = 128 m bf16 + pad]
//   [34816  , 69632 )  As_lo
//       alias after GEMM: ys[64][132] f32 @0 (33792),
//                         w1p[2][9][64] u64 @33792 (9216),
//                         wts_s[128][37] f32 @43008 (18944)
//   [69632  , 87040 )  Ws_hi [64 oc][272B rows = 128 k bf16 + pad]
//   [87040  , 104448)  Ws_lo
//   [104448 , 105280)  consts A0[64] B0[64] A1[40] B1[40]
// ---------------------------------------------------------------------------
#define S_AHI   0
#define S_ALO   34816
#define S_WHI   69632
#define S_WLO   87040
#define S_CST   104448
#define SMEM1   105280
#define S_YS    0
#define S_W1P   33792
#define S_WTS   43008
#define YSTRIDE 132

extern "C" __global__ void __launch_bounds__(256, 2)
k_weights(const float* __restrict__ x,
          const float* __restrict__ w0, const float* __restrict__ b0,
          const float* __restrict__ bn0_g, const float* __restrict__ bn0_b,
          const float* __restrict__ bn0_m, const float* __restrict__ bn0_v,
          const float* __restrict__ w1, const float* __restrict__ b1,
          const float* __restrict__ bn1_g, const float* __restrict__ bn1_b,
          const float* __restrict__ bn1_m, const float* __restrict__ bn1_v)
{
    extern __shared__ char smem[];
    const u32 sb = smem_u32(smem);
    float* cA0 = (float*)(smem + S_CST);
    float* cB0 = cA0 + 64;
    float* cA1 = cB0 + 64;
    float* cB1 = cA1 + 40;
    float* ys    = (float*)(smem + S_YS);
    u64*   w1ps  = (u64*)(smem + S_W1P);
    float* wts_s = (float*)(smem + S_WTS);

    const int t = threadIdx.x;
    const int warp = t >> 5, lane = t & 31;
    const int n = blockIdx.y, p0 = blockIdx.x * 128;

    // fold BN constants
    if (t < 64) {
        float A = bn0_g[t] * rsqrtf(bn0_v[t] + EPS);
        cA0[t] = A;
        cB0[t] = (b0[t] - bn0_m[t]) * A + bn0_b[t];
    } else if (t < 64 + Pp) {
        int i = t - 64;
        float A = bn1_g[i] * rsqrtf(bn1_v[i] + EPS);
        cA1[i] = A;
        cB1[i] = (b1[i] - bn1_m[i]) * A + bn1_b[i];
    }

    // ---- ldmatrix per-lane address offsets (constant) ----
    const int mat = lane >> 3, mr = lane & 7;
    const int m0 = warp * 16;
    // A (trans): mats (k0,m0),(k0,m0+8),(k8,m0),(k8,m0+8); rows = k
    const u32 a_off = (u32)((((mat >> 1) * 8) + mr) * 272 + (m0 + (mat & 1) * 8) * 2);
    // B (non-trans): mats (oc0,k0),(oc0,k8),(oc0+8,k0),(oc0+8,k8); rows = oc
    const u32 b_off = (u32)((((mat >> 1) * 8) + mr) * 272 + (mat & 1) * 16);

    float acc[8][4];
    #pragma unroll
    for (int i = 0; i < 8; i++)
        #pragma unroll
        for (int j = 0; j < 4; j++) acc[i][j] = 0.f;

    // ================= layer0 GEMM: two K-halves =================
    #pragma unroll 1
    for (int h = 0; h < 2; h++) {
        __syncthreads();   // protect As/Ws from previous half's reads

        // ---- stage A: x[k][px] -> As[k][m] bf16 hi/lo (272B rows) ----
        {
            const float2* xr = (const float2*)(x + ((size_t)n * Cc + h * 128 + warp * 16) * HW + p0);
            char* ahb = smem + S_AHI + (warp * 16) * 272 + lane * 4;
            char* alb = smem + S_ALO + (warp * 16) * 272 + lane * 4;
            #pragma unroll 4
            for (int rr = 0; rr < 16; rr++) {
                float2 v0 = xr[lane];
                float2 v1 = xr[lane + 32];
                u32 h0, l0, h1, l1;
                split2(v0.x, v0.y, h0, l0);
                split2(v1.x, v1.y, h1, l1);
                *(u32*)(ahb)       = h0;
                *(u32*)(ahb + 128) = h1;
                *(u32*)(alb)       = l0;
                *(u32*)(alb + 128) = l1;
                xr += HW / 2;
                ahb += 272; alb += 272;
            }
        }
        // ---- stage B: w0[oc][c-half] -> Ws[oc][k] bf16 hi/lo ----
        {
            const int cq = t & 63;            // k-pair index
            #pragma unroll 4
            for (int it = 0; it < 16; it++) {
                int oc = it * 4 + (t >> 6);
                float2 v = *(const float2*)(w0 + (size_t)oc * Cc + h * 128 + cq * 2);
                u32 hi, lo;
                split2(v.x, v.y, hi, lo);
                *(u32*)(smem + S_WHI + oc * 272 + cq * 4) = hi;
                *(u32*)(smem + S_WLO + oc * 272 + cq * 4) = lo;
            }
        }
        __syncthreads();

        // ---- 8 k-steps of m16n8k16, hi/lo split (3 products) ----
        #pragma unroll
        for (int ks = 0; ks < 8; ks++) {
            u32 ah0, ah1, ah2, ah3, al0, al1, al2, al3;
            ldsm4t(ah0, ah1, ah2, ah3, sb + S_AHI + ks * 4352 + a_off);
            ldsm4t(al0, al1, al2, al3, sb + S_ALO + ks * 4352 + a_off);
            #pragma unroll
            for (int j = 0; j < 4; j++) {
                u32 bh0, bh1, bh2, bh3, bl0, bl1, bl2, bl3;
                ldsm4(bh0, bh1, bh2, bh3, sb + S_WHI + j * 16 * 272 + ks * 32 + b_off);
                ldsm4(bl0, bl1, bl2, bl3, sb + S_WLO + j * 16 * 272 + ks * 32 + b_off);
                mma16816(acc[2 * j],     ah0, ah1, ah2, ah3, bh0, bh1);
                mma16816(acc[2 * j],     al0, al1, al2, al3, bh0, bh1);
                mma16816(acc[2 * j],     ah0, ah1, ah2, ah3, bl0, bl1);
                mma16816(acc[2 * j + 1], ah0, ah1, ah2, ah3, bh2, bh3);
                mma16816(acc[2 * j + 1], al0, al1, al2, al3, bh2, bh3);
                mma16816(acc[2 * j + 1], ah0, ah1, ah2, ah3, bl2, bl3);
            }
        }
    }
    __syncthreads();   // GEMM reads done -> safe to alias ys/w1p/wts over As

    // ---- epilogue: BN + ReLU -> ys[oc][px] (f32, stride 132) ----
    {
        const int g = lane >> 2, tq = lane & 3;
        const int pxa = m0 + g, pxb = m0 + g + 8;
        #pragma unroll
        for (int j = 0; j < 8; j++) {
            int oc0 = 8 * j + 2 * tq, oc1 = oc0 + 1;
            float Aa = cA0[oc0], Ba = cB0[oc0];
            float Ab = cA0[oc1], Bb = cB0[oc1];
            ys[oc0 * YSTRIDE + pxa] = fmaxf(fmaf(acc[j][0], Aa, Ba), 0.f);
            ys[oc1 * YSTRIDE + pxa] = fmaxf(fmaf(acc[j][1], Ab, Bb), 0.f);
            ys[oc0 * YSTRIDE + pxb] = fmaxf(fmaf(acc[j][2], Aa, Ba), 0.f);
            ys[oc1 * YSTRIDE + pxb] = fmaxf(fmaf(acc[j][3], Ab, Bb), 0.f);
        }
    }
    // stage w1 packed pairs (alias region, disjoint from ys)
    for (int i = t; i < 2 * 9 * OC; i += 256) {
        int hq = i / (9 * OC), k = (i / OC) % 9, o = i % OC;
        w1ps[i] = pack2(w1[(4 * k + hq) * OC + o], w1[(4 * k + hq + 2) * OC + o]);
    }
    __syncthreads();

    // ---- phase 3: encoder + BN + ReLU + softmax over k ----
    const int px = t & 127;
    const int hh = t >> 7;          // 0 -> u {0,2}, 1 -> u {1,3}
    const u64* wrow = w1ps + hh * 9 * OC;

    u64 a[9];
    #pragma unroll
    for (int k = 0; k < 9; k++) a[k] = 0ULL;

    #pragma unroll 4
    for (int o = 0; o < OC; o++) {
        float yo = ys[o * YSTRIDE + px];
        u64 yp = pack2(yo, yo);
        #pragma unroll
        for (int k = 0; k < 9; k++) fma2(a[k], wrow[k * OC + o], yp);
    }

    float2 e[9];
    float mx0 = -1e30f, mx1 = -1e30f;
    #pragma unroll
    for (int k = 0; k < 9; k++) {
        int c0 = k * 4 + hh, c1 = c0 + 2;
        float2 v = unpack2(a[k]);
        v.x = fmaxf(fmaf(v.x, cA1[c0], cB1[c0]), 0.f);
        v.y = fmaxf(fmaf(v.y, cA1[c1], cB1[c1]), 0.f);
        e[k] = v;
        mx0 = fmaxf(mx0, v.x); mx1 = fmaxf(mx1, v.y);
    }
    float s0 = 0.f, s1 = 0.f;
    #pragma unroll
    for (int k = 0; k < 9; k++) {
        e[k].x = __expf(e[k].x - mx0); s0 += e[k].x;
        e[k].y = __expf(e[k].y - mx1); s1 += e[k].y;
    }
    float i0 = 1.f / s0, i1 = 1.f / s1;
    #pragma unroll
    for (int k = 0; k < 9; k++) {
        wts_s[px * 37 + k * 4 + hh]     = e[k].x * i0;
        wts_s[px * 37 + k * 4 + hh + 2] = e[k].y * i1;
    }
    __syncthreads();

    // ---- phase 4: coalesced dump to g_wts ----
    float4* gdst = (float4*)(g_wts + (size_t)(n * HW + p0) * Pp);
    for (int i4 = t; i4 < (128 * Pp) / 4; i4 += 256) {
        float4 v;
        int lin = i4 * 4;
        v.x = wts_s[(lin    ) / 36 * 37 + (lin    ) % 36];
        v.y = wts_s[(lin + 1) / 36 * 37 + (lin + 1) % 36];
        v.z = wts_s[(lin + 2) / 36 * 37 + (lin + 2) % 36];
        v.w = wts_s[(lin + 3) / 36 * 37 + (lin + 3) % 36];
        gdst[i4] = v;
    }
}

// ---------------------------------------------------------------------------
// Kernel 2: reassembly + pixelshuffle (unchanged from R4).
// ---------------------------------------------------------------------------
__device__ __forceinline__ void cp_async4(u32 dst, const void* src, bool ok) {
    asm volatile("cp.async.ca.shared.global [%0], [%1], 4, %2;"
                 :: "r"(dst), "l"(src), "r"(ok ? 4 : 0));
}
__device__ __forceinline__ void cp_commit() { asm volatile("cp.async.commit_group;"); }
__device__ __forceinline__ void cp_wait_all() { asm volatile("cp.async.wait_group 0;" ::: "memory"); }
__device__ __forceinline__ void stcs2(float* p, float2 v) {
    asm volatile("st.global.cs.v2.f32 [%0], {%1,%2};" :: "l"(p), "f"(v.x), "f"(v.y));
}

#define CHUNK_B (8 * 10 * 34 * 4)

extern "C" __global__ void __launch_bounds__(256)
k_reassemble(const float* __restrict__ x, float* __restrict__ out)
{
    __shared__ float xs[2][8][10][34];

    const int tid = threadIdx.x;
    const int tx   = tid & 31;
    const int warp = tid >> 5;
    const int w0p = blockIdx.x * 32;
    const int h0  = blockIdx.y * 8;
    const int n   = blockIdx.z >> 3;
    const int c0  = (blockIdx.z & 7) * 32;
    const int h   = h0 + warp;
    const int w   = w0p + tx;

    const float* xb = x + (size_t)n * Cc * HW;
    u32 s_base = (u32)__cvta_generic_to_shared(&xs[0][0][0][0]);

    const bool col1ok = (w0p + tx - 1) >= 0 && (w0p + tx - 1) < Ww;
    const bool do2    = (tx < 2);
    const bool col2ok = do2 && ((w0p - 1 + tx + 32) < Ww);
    const float* gBase = xb + (size_t)(c0 + warp) * HW + (h0 - 1) * Ww + (w0p - 1 + tx);
    const u32    sRow0 = s_base + (warp * 10 * 34 + tx) * 4;

    {
        const float* g = gBase;
        u32 s = sRow0;
        #pragma unroll
        for (int r = 0; r < 10; r++) {
            bool rok = ((unsigned)(h0 - 1 + r) < (unsigned)Hh);
            cp_async4(s, rok && col1ok ? g : xb, rok && col1ok);
            if (do2) cp_async4(s + 128, rok && col2ok ? g + 32 : xb, rok && col2ok);
            g += Ww; s += 136;
        }
        cp_commit();
    }

    const float4* wp4 = (const float4*)(g_wts + (size_t)(n * HW + h * Ww + w) * Pp);
    u64 wp01[9], wp23[9];
    #pragma unroll
    for (int k = 0; k < 9; k++) {
        float4 v = __ldg(wp4 + k);
        wp01[k] = pack2(v.x, v.y);
        wp23[k] = pack2(v.z, v.w);
    }

    const int ty = tid >> 5;
    float* op = out + (size_t)n * Cc * (HW * 4)
                    + (size_t)c0 * (HW * 4) + (2 * h) * 128 + 2 * w;

    for (int ch8 = 0; ch8 < 4; ch8++) {
        cp_wait_all();
        __syncthreads();

        if (ch8 < 3) {
            const float* g = gBase + (size_t)(ch8 + 1) * 8 * HW;
            u32 s = sRow0 + ((ch8 + 1) & 1) * CHUNK_B;
            #pragma unroll
            for (int r = 0; r < 10; r++) {
                bool rok = ((unsigned)(h0 - 1 + r) < (unsigned)Hh);
                cp_async4(s, rok && col1ok ? g : xb, rok && col1ok);
                if (do2) cp_async4(s + 128, rok && col2ok ? g + 32 : xb, rok && col2ok);
                g += Ww; s += 136;
            }
            cp_commit();
        }

        const int b = ch8 & 1;
        #pragma unroll
        for (int cl = 0; cl < 8; cl++) {
            u64 a01 = 0ULL, a23 = 0ULL;
            #pragma unroll
            for (int dy = 0; dy < 3; dy++) {
                #pragma unroll
                for (int dx = 0; dx < 3; dx++) {
                    float xv = xs[b][cl][ty + dy][tx + dx];
                    u64 xp = pack2(xv, xv);
                    int k = dy * 3 + dx;
                    fma2(a01, xp, wp01[k]);
                    fma2(a23, xp, wp23[k]);
                }
            }
            stcs2(op,       unpack2(a01));
            stcs2(op + 128, unpack2(a23));
            op += HW * 4;
        }
    }
}

extern "C" void kernel_launch(void* const* d_in, const int* in_sizes, int n_in,
                              void* d_out, int out_size)
{
    const float* x     = (const float*)d_in[0];
    const float* w0    = (const float*)d_in[1];
    const float* b0    = (const float*)d_in[2];
    const float* bn0_g = (const float*)d_in[3];
    const float* bn0_b = (const float*)d_in[4];
    const float* bn0_m = (const float*)d_in[5];
    const float* bn0_v = (const float*)d_in[6];
    const float* w1    = (const float*)d_in[7];
    const float* b1    = (const float*)d_in[8];
    const float* bn1_g = (const float*)d_in[9];
    const float* bn1_b = (const float*)d_in[10];
    const float* bn1_m = (const float*)d_in[11];
    const float* bn1_v = (const float*)d_in[12];
    float* out = (float*)d_out;

    cudaFuncSetAttribute(k_weights, cudaFuncAttributeMaxDynamicSharedMemorySize, SMEM1);
    dim3 g1(32, Nn);
    k_weights<<<g1, 256, SMEM1>>>(x, w0, b0, bn0_g, bn0_b, bn0_m, bn0_v,
                                  w1, b1, bn1_g, bn1_b, bn1_m, bn1_v);

    dim3 g2(2, 8, Nn * 8);
    k_reassemble<<<g2, 256>>>(x, out);
}

// round 7
// speedup vs baseline: 2.2208x; 1.0370x over previous
#include <cuda_runtime.h>
#include <cstdint>

#define EPS 1e-5f
#define Nn 8
#define Cc 256
#define Hh 64
#define Ww 64
#define HW 4096
#define OC 64
#define Pp 36

typedef unsigned long long u64;
typedef unsigned int u32;
typedef unsigned short u16;

// softmax weights scratch: [n][px][36]
__device__ float g_wts[(size_t)Nn * HW * Pp];

__device__ __forceinline__ u64 pack2(float x, float y) {
    u64 r; asm("mov.b64 %0, {%1,%2};" : "=l"(r) : "f"(x), "f"(y)); return r;
}
__device__ __forceinline__ void fma2(u64 &d, u64 a, u64 b) {
    asm("fma.rn.f32x2 %0, %1, %2, %0;" : "+l"(d) : "l"(a), "l"(b));
}
__device__ __forceinline__ float2 unpack2(u64 v) {
    float2 r; asm("mov.b64 {%0,%1}, %2;" : "=f"(r.x), "=f"(r.y) : "l"(v)); return r;
}
__device__ __forceinline__ u32 smem_u32(const void* p) {
    u32 a;
    asm("{ .reg .u64 t; cvta.to.shared.u64 t, %1; cvt.u32.u64 %0, t; }" : "=r"(a) : "l"(p));
    return a;
}
__device__ __forceinline__ void ldsm4(u32& r0, u32& r1, u32& r2, u32& r3, u32 addr) {
    asm volatile("ldmatrix.sync.aligned.m8n8.x4.shared.b16 {%0,%1,%2,%3}, [%4];"
                 : "=r"(r0), "=r"(r1), "=r"(r2), "=r"(r3) : "r"(addr));
}
__device__ __forceinline__ void ldsm4t(u32& r0, u32& r1, u32& r2, u32& r3, u32 addr) {
    asm volatile("ldmatrix.sync.aligned.m8n8.x4.trans.shared.b16 {%0,%1,%2,%3}, [%4];"
                 : "=r"(r0), "=r"(r1), "=r"(r2), "=r"(r3) : "r"(addr));
}
__device__ __forceinline__ void mma16816(float* c, u32 a0, u32 a1, u32 a2, u32 a3,
                                          u32 b0, u32 b1) {
    asm volatile("mma.sync.aligned.m16n8k16.row.col.f32.bf16.bf16.f32 "
                 "{%0,%1,%2,%3}, {%4,%5,%6,%7}, {%8,%9}, {%0,%1,%2,%3};"
                 : "+f"(c[0]), "+f"(c[1]), "+f"(c[2]), "+f"(c[3])
                 : "r"(a0), "r"(a1), "r"(a2), "r"(a3), "r"(b0), "r"(b1));
}
__device__ __forceinline__ void split2(float vx, float vy, u32& hi, u32& lo) {
    u32 h; asm("cvt.rn.bf16x2.f32 %0, %1, %2;" : "=r"(h) : "f"(vy), "f"(vx));
    float hx = __uint_as_float(h << 16);
    float hy = __uint_as_float(h & 0xffff0000u);
    u32 l; asm("cvt.rn.bf16x2.f32 %0, %1, %2;" : "=r"(l) : "f"(vy - hy), "f"(vx - hx));
    hi = h; lo = l;
}

// ---------------------------------------------------------------------------
// Kernel 1: per-pixel weight computation (unchanged from R6).
// ---------------------------------------------------------------------------
#define S_AHI   0
#define S_ALO   34816
#define S_WHI   69632
#define S_WLO   87040
#define S_CST   104448
#define SMEM1   105280
#define S_YS    0
#define S_W1P   33792
#define S_WTS   43008
#define YSTRIDE 132

extern "C" __global__ void __launch_bounds__(256, 2)
k_weights(const float* __restrict__ x,
          const float* __restrict__ w0, const float* __restrict__ b0,
          const float* __restrict__ bn0_g, const float* __restrict__ bn0_b,
          const float* __restrict__ bn0_m, const float* __restrict__ bn0_v,
          const float* __restrict__ w1, const float* __restrict__ b1,
          const float* __restrict__ bn1_g, const float* __restrict__ bn1_b,
          const float* __restrict__ bn1_m, const float* __restrict__ bn1_v)
{
    extern __shared__ char smem[];
    const u32 sb = smem_u32(smem);
    float* cA0 = (float*)(smem + S_CST);
    float* cB0 = cA0 + 64;
    float* cA1 = cB0 + 64;
    float* cB1 = cA1 + 40;
    float* ys    = (float*)(smem + S_YS);
    u64*   w1ps  = (u64*)(smem + S_W1P);
    float* wts_s = (float*)(smem + S_WTS);

    const int t = threadIdx.x;
    const int warp = t >> 5, lane = t & 31;
    const int n = blockIdx.y, p0 = blockIdx.x * 128;

    if (t < 64) {
        float A = bn0_g[t] * rsqrtf(bn0_v[t] + EPS);
        cA0[t] = A;
        cB0[t] = (b0[t] - bn0_m[t]) * A + bn0_b[t];
    } else if (t < 64 + Pp) {
        int i = t - 64;
        float A = bn1_g[i] * rsqrtf(bn1_v[i] + EPS);
        cA1[i] = A;
        cB1[i] = (b1[i] - bn1_m[i]) * A + bn1_b[i];
    }

    const int mat = lane >> 3, mr = lane & 7;
    const int m0 = warp * 16;
    const u32 a_off = (u32)((((mat >> 1) * 8) + mr) * 272 + (m0 + (mat & 1) * 8) * 2);
    const u32 b_off = (u32)((((mat >> 1) * 8) + mr) * 272 + (mat & 1) * 16);

    float acc[8][4];
    #pragma unroll
    for (int i = 0; i < 8; i++)
        #pragma unroll
        for (int j = 0; j < 4; j++) acc[i][j] = 0.f;

    #pragma unroll 1
    for (int h = 0; h < 2; h++) {
        __syncthreads();
        {
            const float2* xr = (const float2*)(x + ((size_t)n * Cc + h * 128 + warp * 16) * HW + p0);
            char* ahb = smem + S_AHI + (warp * 16) * 272 + lane * 4;
            char* alb = smem + S_ALO + (warp * 16) * 272 + lane * 4;
            #pragma unroll 4
            for (int rr = 0; rr < 16; rr++) {
                float2 v0 = xr[lane];
                float2 v1 = xr[lane + 32];
                u32 h0, l0, h1, l1;
                split2(v0.x, v0.y, h0, l0);
                split2(v1.x, v1.y, h1, l1);
                *(u32*)(ahb)       = h0;
                *(u32*)(ahb + 128) = h1;
                *(u32*)(alb)       = l0;
                *(u32*)(alb + 128) = l1;
                xr += HW / 2;
                ahb += 272; alb += 272;
            }
        }
        {
            const int cq = t & 63;
            #pragma unroll 4
            for (int it = 0; it < 16; it++) {
                int oc = it * 4 + (t >> 6);
                float2 v = *(const float2*)(w0 + (size_t)oc * Cc + h * 128 + cq * 2);
                u32 hi, lo;
                split2(v.x, v.y, hi, lo);
                *(u32*)(smem + S_WHI + oc * 272 + cq * 4) = hi;
                *(u32*)(smem + S_WLO + oc * 272 + cq * 4) = lo;
            }
        }
        __syncthreads();

        #pragma unroll
        for (int ks = 0; ks < 8; ks++) {
            u32 ah0, ah1, ah2, ah3, al0, al1, al2, al3;
            ldsm4t(ah0, ah1, ah2, ah3, sb + S_AHI + ks * 4352 + a_off);
            ldsm4t(al0, al1, al2, al3, sb + S_ALO + ks * 4352 + a_off);
            #pragma unroll
            for (int j = 0; j < 4; j++) {
                u32 bh0, bh1, bh2, bh3, bl0, bl1, bl2, bl3;
                ldsm4(bh0, bh1, bh2, bh3, sb + S_WHI + j * 16 * 272 + ks * 32 + b_off);
                ldsm4(bl0, bl1, bl2, bl3, sb + S_WLO + j * 16 * 272 + ks * 32 + b_off);
                mma16816(acc[2 * j],     ah0, ah1, ah2, ah3, bh0, bh1);
                mma16816(acc[2 * j],     al0, al1, al2, al3, bh0, bh1);
                mma16816(acc[2 * j],     ah0, ah1, ah2, ah3, bl0, bl1);
                mma16816(acc[2 * j + 1], ah0, ah1, ah2, ah3, bh2, bh3);
                mma16816(acc[2 * j + 1], al0, al1, al2, al3, bh2, bh3);
                mma16816(acc[2 * j + 1], ah0, ah1, ah2, ah3, bl2, bl3);
            }
        }
    }
    __syncthreads();

    {
        const int g = lane >> 2, tq = lane & 3;
        const int pxa = m0 + g, pxb = m0 + g + 8;
        #pragma unroll
        for (int j = 0; j < 8; j++) {
            int oc0 = 8 * j + 2 * tq, oc1 = oc0 + 1;
            float Aa = cA0[oc0], Ba = cB0[oc0];
            float Ab = cA0[oc1], Bb = cB0[oc1];
            ys[oc0 * YSTRIDE + pxa] = fmaxf(fmaf(acc[j][0], Aa, Ba), 0.f);
            ys[oc1 * YSTRIDE + pxa] = fmaxf(fmaf(acc[j][1], Ab, Bb), 0.f);
            ys[oc0 * YSTRIDE + pxb] = fmaxf(fmaf(acc[j][2], Aa, Ba), 0.f);
            ys[oc1 * YSTRIDE + pxb] = fmaxf(fmaf(acc[j][3], Ab, Bb), 0.f);
        }
    }
    for (int i = t; i < 2 * 9 * OC; i += 256) {
        int hq = i / (9 * OC), k = (i / OC) % 9, o = i % OC;
        w1ps[i] = pack2(w1[(4 * k + hq) * OC + o], w1[(4 * k + hq + 2) * OC + o]);
    }
    __syncthreads();

    const int px = t & 127;
    const int hh = t >> 7;
    const u64* wrow = w1ps + hh * 9 * OC;

    u64 a[9];
    #pragma unroll
    for (int k = 0; k < 9; k++) a[k] = 0ULL;

    #pragma unroll 4
    for (int o = 0; o < OC; o++) {
        float yo = ys[o * YSTRIDE + px];
        u64 yp = pack2(yo, yo);
        #pragma unroll
        for (int k = 0; k < 9; k++) fma2(a[k], wrow[k * OC + o], yp);
    }

    float2 e[9];
    float mx0 = -1e30f, mx1 = -1e30f;
    #pragma unroll
    for (int k = 0; k < 9; k++) {
        int c0 = k * 4 + hh, c1 = c0 + 2;
        float2 v = unpack2(a[k]);
        v.x = fmaxf(fmaf(v.x, cA1[c0], cB1[c0]), 0.f);
        v.y = fmaxf(fmaf(v.y, cA1[c1], cB1[c1]), 0.f);
        e[k] = v;
        mx0 = fmaxf(mx0, v.x); mx1 = fmaxf(mx1, v.y);
    }
    float s0 = 0.f, s1 = 0.f;
    #pragma unroll
    for (int k = 0; k < 9; k++) {
        e[k].x = __expf(e[k].x - mx0); s0 += e[k].x;
        e[k].y = __expf(e[k].y - mx1); s1 += e[k].y;
    }
    float i0 = 1.f / s0, i1 = 1.f / s1;
    #pragma unroll
    for (int k = 0; k < 9; k++) {
        wts_s[px * 37 + k * 4 + hh]     = e[k].x * i0;
        wts_s[px * 37 + k * 4 + hh + 2] = e[k].y * i1;
    }
    __syncthreads();

    float4* gdst = (float4*)(g_wts + (size_t)(n * HW + p0) * Pp);
    for (int i4 = t; i4 < (128 * Pp) / 4; i4 += 256) {
        float4 v;
        int lin = i4 * 4;
        v.x = wts_s[(lin    ) / 36 * 37 + (lin    ) % 36];
        v.y = wts_s[(lin + 1) / 36 * 37 + (lin + 1) % 36];
        v.z = wts_s[(lin + 2) / 36 * 37 + (lin + 2) % 36];
        v.w = wts_s[(lin + 3) / 36 * 37 + (lin + 3) % 36];
        gdst[i4] = v;
    }
}

// ---------------------------------------------------------------------------
// Kernel 2: reassembly + pixelshuffle. 16B cp.async halo (3.4x fewer LDGSTS),
// all loader geometry hoisted to registers.
// ---------------------------------------------------------------------------
__device__ __forceinline__ void cp_async16(u32 dst, const void* src, u32 srcsz) {
    asm volatile("cp.async.cg.shared.global [%0], [%1], 16, %2;"
                 :: "r"(dst), "l"(src), "r"(srcsz));
}
__device__ __forceinline__ void cp_commit() { asm volatile("cp.async.commit_group;"); }
__device__ __forceinline__ void cp_wait_all() { asm volatile("cp.async.wait_group 0;" ::: "memory"); }
__device__ __forceinline__ void stcs2(float* p, float2 v) {
    asm volatile("st.global.cs.v2.f32 [%0], {%1,%2};" :: "l"(p), "f"(v.x), "f"(v.y));
}

#define ROWF    40                          // floats per smem halo row
#define CHUNK_B (8 * 10 * ROWF * 4)         // 12800 B per buffer

extern "C" __global__ void __launch_bounds__(256)
k_reassemble(const float* __restrict__ x, float* __restrict__ out)
{
    __shared__ float xs[2][8][10][ROWF];

    const int tid = threadIdx.x;
    const int tx   = tid & 31;
    const int warp = tid >> 5;
    const int w0p = blockIdx.x * 32;
    const int h0  = blockIdx.y * 8;
    const int n   = blockIdx.z >> 3;
    const int c0  = (blockIdx.z & 7) * 32;
    const int h   = h0 + warp;
    const int w   = w0p + tx;

    const float* xb = x + (size_t)n * Cc * HW;
    u32 s_base = (u32)__cvta_generic_to_shared(&xs[0][0][0][0]);

    // ---- hoisted loader descriptors: warp = channel-in-chunk; 100 float4
    //      slots (10 rows x 10 vec4) covered by 4 predicated ops/lane ----
    // channel-row-0 base pointer (col w0p-4, row h0-1), 16B aligned:
    const float* gWarp = xb + (size_t)(c0 + warp) * HW + (h0 - 1) * Ww + (w0p - 4);
    u32  smOff[4];          // smem byte offset within this warp's channel rows
    int  gOff[4];           // global element offset from gWarp
    bool pred[4], act[4];
    #pragma unroll
    for (int i = 0; i < 4; i++) {
        int idx = i * 32 + tx;
        act[i] = idx < 100;
        int row = idx / 10, j = idx - row * 10;
        int v = w0p - 4 + 4 * j;
        bool rok = ((unsigned)(h0 - 1 + row) < (unsigned)Hh);
        bool cok = ((unsigned)v <= 60u);
        pred[i]  = act[i] && rok && cok;
        smOff[i] = (u32)((warp * 10 * ROWF + row * ROWF + 4 * j) * 4);
        gOff[i]  = row * Ww + 4 * j;
    }

    // ---- prefetch chunk 0 ----
    #pragma unroll
    for (int i = 0; i < 4; i++)
        if (act[i]) cp_async16(s_base + smOff[i], pred[i] ? gWarp + gOff[i] : xb,
                               pred[i] ? 16u : 0u);
    cp_commit();

    // this pixel's 36 softmax weights (overlaps with prefetch)
    const float4* wp4 = (const float4*)(g_wts + (size_t)(n * HW + h * Ww + w) * Pp);
    u64 wp01[9], wp23[9];
    #pragma unroll
    for (int k = 0; k < 9; k++) {
        float4 v = __ldg(wp4 + k);
        wp01[k] = pack2(v.x, v.y);
        wp23[k] = pack2(v.z, v.w);
    }

    const int ty = warp;
    float* op = out + (size_t)n * Cc * (HW * 4)
                    + (size_t)c0 * (HW * 4) + (2 * h) * 128 + 2 * w;

    for (int ch8 = 0; ch8 < 4; ch8++) {
        cp_wait_all();
        __syncthreads();

        if (ch8 < 3) {
            const float* g = gWarp + (size_t)(ch8 + 1) * 8 * HW;
            u32 sb2 = s_base + ((ch8 + 1) & 1) * CHUNK_B;
            #pragma unroll
            for (int i = 0; i < 4; i++)
                if (act[i]) cp_async16(sb2 + smOff[i], pred[i] ? g + gOff[i] : xb,
                                       pred[i] ? 16u : 0u);
            cp_commit();
        }

        const int b = ch8 & 1;
        #pragma unroll
        for (int cl = 0; cl < 8; cl++) {
            u64 a01 = 0ULL, a23 = 0ULL;
            #pragma unroll
            for (int dy = 0; dy < 3; dy++) {
                #pragma unroll
                for (int dx = 0; dx < 3; dx++) {
                    float xv = xs[b][cl][ty + dy][tx + 3 + dx];
                    u64 xp = pack2(xv, xv);
                    int k = dy * 3 + dx;
                    fma2(a01, xp, wp01[k]);
                    fma2(a23, xp, wp23[k]);
                }
            }
            stcs2(op,       unpack2(a01));
            stcs2(op + 128, unpack2(a23));
            op += HW * 4;
        }
    }
}

extern "C" void kernel_launch(void* const* d_in, const int* in_sizes, int n_in,
                              void* d_out, int out_size)
{
    const float* x     = (const float*)d_in[0];
    const float* w0    = (const float*)d_in[1];
    const float* b0    = (const float*)d_in[2];
    const float* bn0_g = (const float*)d_in[3];
    const float* bn0_b = (const float*)d_in[4];
    const float* bn0_m = (const float*)d_in[5];
    const float* bn0_v = (const float*)d_in[6];
    const float* w1    = (const float*)d_in[7];
    const float* b1    = (const float*)d_in[8];
    const float* bn1_g = (const float*)d_in[9];
    const float* bn1_b = (const float*)d_in[10];
    const float* bn1_m = (const float*)d_in[11];
    const float* bn1_v = (const float*)d_in[12];
    float* out = (float*)d_out;

    cudaFuncSetAttribute(k_weights, cudaFuncAttributeMaxDynamicSharedMemorySize, SMEM1);
    dim3 g1(32, Nn);
    k_weights<<<g1, 256, SMEM1>>>(x, w0, b0, bn0_g, bn0_b, bn0_m, bn0_v,
                                  w1, b1, bn1_g, bn1_b, bn1_m, bn1_v);

    dim3 g2(2, 8, Nn * 8);
    k_reassemble<<<g2, 256>>>(x, out);
}

// round 8
// speedup vs baseline: 2.3983x; 1.0799x over previous
#include <cuda_runtime.h>
#include <cstdint>

#define EPS 1e-5f
#define Nn 8
#define Cc 256
#define Hh 64
#define Ww 64
#define HW 4096
#define OC 64
#define Pp 36

typedef unsigned long long u64;
typedef unsigned int u32;
typedef unsigned short u16;

// softmax weights scratch: [n][px][36]
__device__ float g_wts[(size_t)Nn * HW * Pp];

__device__ __forceinline__ u64 pack2(float x, float y) {
    u64 r; asm("mov.b64 %0, {%1,%2};" : "=l"(r) : "f"(x), "f"(y)); return r;
}
__device__ __forceinline__ void fma2(u64 &d, u64 a, u64 b) {
    asm("fma.rn.f32x2 %0, %1, %2, %0;" : "+l"(d) : "l"(a), "l"(b));
}
__device__ __forceinline__ float2 unpack2(u64 v) {
    float2 r; asm("mov.b64 {%0,%1}, %2;" : "=f"(r.x), "=f"(r.y) : "l"(v)); return r;
}
__device__ __forceinline__ u32 smem_u32(const void* p) {
    u32 a;
    asm("{ .reg .u64 t; cvta.to.shared.u64 t, %1; cvt.u32.u64 %0, t; }" : "=r"(a) : "l"(p));
    return a;
}
__device__ __forceinline__ void ldsm4(u32& r0, u32& r1, u32& r2, u32& r3, u32 addr) {
    asm volatile("ldmatrix.sync.aligned.m8n8.x4.shared.b16 {%0,%1,%2,%3}, [%4];"
                 : "=r"(r0), "=r"(r1), "=r"(r2), "=r"(r3) : "r"(addr));
}
__device__ __forceinline__ void ldsm4t(u32& r0, u32& r1, u32& r2, u32& r3, u32 addr) {
    asm volatile("ldmatrix.sync.aligned.m8n8.x4.trans.shared.b16 {%0,%1,%2,%3}, [%4];"
                 : "=r"(r0), "=r"(r1), "=r"(r2), "=r"(r3) : "r"(addr));
}
__device__ __forceinline__ void mma16816(float* c, u32 a0, u32 a1, u32 a2, u32 a3,
                                          u32 b0, u32 b1) {
    asm volatile("mma.sync.aligned.m16n8k16.row.col.f32.bf16.bf16.f32 "
                 "{%0,%1,%2,%3}, {%4,%5,%6,%7}, {%8,%9}, {%0,%1,%2,%3};"
                 : "+f"(c[0]), "+f"(c[1]), "+f"(c[2]), "+f"(c[3])
                 : "r"(a0), "r"(a1), "r"(a2), "r"(a3), "r"(b0), "r"(b1));
}
__device__ __forceinline__ void split2(float vx, float vy, u32& hi, u32& lo) {
    u32 h; asm("cvt.rn.bf16x2.f32 %0, %1, %2;" : "=r"(h) : "f"(vy), "f"(vx));
    float hx = __uint_as_float(h << 16);
    float hy = __uint_as_float(h & 0xffff0000u);
    u32 l; asm("cvt.rn.bf16x2.f32 %0, %1, %2;" : "=r"(l) : "f"(vy - hy), "f"(vx - hx));
    hi = h; lo = l;
}
__device__ __forceinline__ u16 bf16hi(float v) {
    u16 h; asm("cvt.rn.bf16.f32 %0, %1;" : "=h"(h) : "f"(v)); return h;
}

// ---------------------------------------------------------------------------
// Kernel 1: weights. GEMM0 + encoder both on mma.sync (bf16 hi/lo split).
// smem phase 1 (GEMM0): As_hi/As_lo [128k][272B], Ws_hi/Ws_lo [64oc][272B]
// smem phase 2 (encoder, aliased):
//   As2 hi/lo [64 oc-k][272B], Ws2 hi/lo [48 p][272B], L [128][49] f32,
//   wts_s [128][37] f32 (@0, written after MMA1 reads complete)
// ---------------------------------------------------------------------------
#define S_AHI   0
#define S_ALO   34816
#define S_WHI   69632
#define S_WLO   87040
#define S_CST   104448
#define SMEM1   105280

#define S2_AHI  0
#define S2_ALO  17408
#define S2_WHI  34816
#define S2_WLO  47872
#define S2_L    60928
#define S2_WTS  0

extern "C" __global__ void __launch_bounds__(256, 2)
k_weights(const float* __restrict__ x,
          const float* __restrict__ w0, const float* __restrict__ b0,
          const float* __restrict__ bn0_g, const float* __restrict__ bn0_b,
          const float* __restrict__ bn0_m, const float* __restrict__ bn0_v,
          const float* __restrict__ w1, const float* __restrict__ b1,
          const float* __restrict__ bn1_g, const float* __restrict__ bn1_b,
          const float* __restrict__ bn1_m, const float* __restrict__ bn1_v)
{
    extern __shared__ char smem[];
    const u32 sb = smem_u32(smem);
    float* cA0 = (float*)(smem + S_CST);
    float* cB0 = cA0 + 64;
    float* cA1 = cB0 + 64;
    float* cB1 = cA1 + 40;
    float* wts_s = (float*)(smem + S2_WTS);
    float* L     = (float*)(smem + S2_L);

    const int t = threadIdx.x;
    const int warp = t >> 5, lane = t & 31;
    const int n = blockIdx.y, p0 = blockIdx.x * 128;

    if (t < 64) {
        float A = bn0_g[t] * rsqrtf(bn0_v[t] + EPS);
        cA0[t] = A;
        cB0[t] = (b0[t] - bn0_m[t]) * A + bn0_b[t];
    } else if (t < 64 + 40) {
        int i = t - 64;
        if (i < Pp) {
            float A = bn1_g[i] * rsqrtf(bn1_v[i] + EPS);
            cA1[i] = A;
            cB1[i] = (b1[i] - bn1_m[i]) * A + bn1_b[i];
        } else { cA1[i] = 0.f; cB1[i] = 0.f; }
    }

    // prefetch w1 into registers (staged to smem after GEMM0)
    float2 w1r[5];
    #pragma unroll
    for (int r = 0; r < 5; r++) {
        int i = t + 256 * r;                 // 1280 float2 total
        w1r[r] = *(const float2*)(w1 + (i >> 5) * OC + (i & 31) * 2);
    }

    const int mat = lane >> 3, mr = lane & 7;
    const int m0 = warp * 16;
    const int g  = lane >> 2, tq = lane & 3;
    const u32 a_off = (u32)((((mat >> 1) * 8) + mr) * 272 + (m0 + (mat & 1) * 8) * 2);
    const u32 b_off = (u32)((((mat >> 1) * 8) + mr) * 272 + (mat & 1) * 16);

    float acc[8][4];
    #pragma unroll
    for (int i = 0; i < 8; i++)
        #pragma unroll
        for (int j = 0; j < 4; j++) acc[i][j] = 0.f;

    // ================= GEMM0: two K-halves =================
    #pragma unroll 1
    for (int h = 0; h < 2; h++) {
        __syncthreads();
        {
            const float2* xr = (const float2*)(x + ((size_t)n * Cc + h * 128 + warp * 16) * HW + p0);
            char* ahb = smem + S_AHI + (warp * 16) * 272 + lane * 4;
            char* alb = smem + S_ALO + (warp * 16) * 272 + lane * 4;
            #pragma unroll 4
            for (int rr = 0; rr < 16; rr++) {
                float2 v0 = xr[lane];
                float2 v1 = xr[lane + 32];
                u32 h0, l0, h1, l1;
                split2(v0.x, v0.y, h0, l0);
                split2(v1.x, v1.y, h1, l1);
                *(u32*)(ahb)       = h0;
                *(u32*)(ahb + 128) = h1;
                *(u32*)(alb)       = l0;
                *(u32*)(alb + 128) = l1;
                xr += HW / 2;
                ahb += 272; alb += 272;
            }
        }
        {
            const int cq = t & 63;
            #pragma unroll 4
            for (int it = 0; it < 16; it++) {
                int oc = it * 4 + (t >> 6);
                float2 v = *(const float2*)(w0 + (size_t)oc * Cc + h * 128 + cq * 2);
                u32 hi, lo;
                split2(v.x, v.y, hi, lo);
                *(u32*)(smem + S_WHI + oc * 272 + cq * 4) = hi;
                *(u32*)(smem + S_WLO + oc * 272 + cq * 4) = lo;
            }
        }
        __syncthreads();

        #pragma unroll
        for (int ks = 0; ks < 8; ks++) {
            u32 ah0, ah1, ah2, ah3, al0, al1, al2, al3;
            ldsm4t(ah0, ah1, ah2, ah3, sb + S_AHI + ks * 4352 + a_off);
            ldsm4t(al0, al1, al2, al3, sb + S_ALO + ks * 4352 + a_off);
            #pragma unroll
            for (int j = 0; j < 4; j++) {
                u32 bh0, bh1, bh2, bh3, bl0, bl1, bl2, bl3;
                ldsm4(bh0, bh1, bh2, bh3, sb + S_WHI + j * 16 * 272 + ks * 32 + b_off);
                ldsm4(bl0, bl1, bl2, bl3, sb + S_WLO + j * 16 * 272 + ks * 32 + b_off);
                mma16816(acc[2 * j],     ah0, ah1, ah2, ah3, bh0, bh1);
                mma16816(acc[2 * j],     al0, al1, al2, al3, bh0, bh1);
                mma16816(acc[2 * j],     ah0, ah1, ah2, ah3, bl0, bl1);
                mma16816(acc[2 * j + 1], ah0, ah1, ah2, ah3, bh2, bh3);
                mma16816(acc[2 * j + 1], al0, al1, al2, al3, bh2, bh3);
                mma16816(acc[2 * j + 1], ah0, ah1, ah2, ah3, bl2, bl3);
            }
        }
    }
    __syncthreads();   // GEMM0 operand reads done -> alias phase-2 regions

    // ---- epilogue: BN0 + ReLU -> As2[oc][px] bf16 hi/lo directly ----
    {
        const int pxa = m0 + g, pxb = m0 + g + 8;
        #pragma unroll
        for (int j = 0; j < 8; j++) {
            int oc0 = 8 * j + 2 * tq, oc1 = oc0 + 1;
            float Aa = cA0[oc0], Ba = cB0[oc0];
            float Ab = cA0[oc1], Bb = cB0[oc1];
            float v00 = fmaxf(fmaf(acc[j][0], Aa, Ba), 0.f);   // (pxa, oc0)
            float v01 = fmaxf(fmaf(acc[j][1], Ab, Bb), 0.f);   // (pxa, oc1)
            float v10 = fmaxf(fmaf(acc[j][2], Aa, Ba), 0.f);   // (pxb, oc0)
            float v11 = fmaxf(fmaf(acc[j][3], Ab, Bb), 0.f);   // (pxb, oc1)
            #pragma unroll
            for (int q = 0; q < 4; q++) {
                float v  = (q == 0) ? v00 : (q == 1) ? v01 : (q == 2) ? v10 : v11;
                int oc   = (q & 1) ? oc1 : oc0;
                int px   = (q & 2) ? pxb : pxa;
                u16 hi = bf16hi(v);
                float hf = __uint_as_float(((u32)hi) << 16);
                u16 lo = bf16hi(v - hf);
                *(u16*)(smem + S2_AHI + oc * 272 + px * 2) = hi;
                *(u16*)(smem + S2_ALO + oc * 272 + px * 2) = lo;
            }
        }
    }
    // ---- stage Ws2 from prefetched w1 regs ----
    #pragma unroll
    for (int r = 0; r < 5; r++) {
        int i = t + 256 * r;
        int p = i >> 5, oq = i & 31;
        u32 hi, lo;
        split2(w1r[r].x, w1r[r].y, hi, lo);
        *(u32*)(smem + S2_WHI + p * 272 + oq * 4) = hi;
        *(u32*)(smem + S2_WLO + p * 272 + oq * 4) = lo;
    }
    // zero pad rows 40-47
    for (int i = t; i < 8 * 68; i += 256) {
        int row = 40 + i / 68, col = i % 68;
        *(u32*)(smem + S2_WHI + row * 272 + col * 4) = 0;
        *(u32*)(smem + S2_WLO + row * 272 + col * 4) = 0;
    }
    __syncthreads();

    // ================= MMA1: logits [128, 40] =================
    float d1[5][4];
    #pragma unroll
    for (int i = 0; i < 5; i++)
        #pragma unroll
        for (int j = 0; j < 4; j++) d1[i][j] = 0.f;

    #pragma unroll
    for (int ks = 0; ks < 4; ks++) {
        u32 ah0, ah1, ah2, ah3, al0, al1, al2, al3;
        ldsm4t(ah0, ah1, ah2, ah3, sb + S2_AHI + ks * 4352 + a_off);
        ldsm4t(al0, al1, al2, al3, sb + S2_ALO + ks * 4352 + a_off);
        #pragma unroll
        for (int rb = 0; rb < 3; rb++) {
            u32 bh0, bh1, bh2, bh3, bl0, bl1, bl2, bl3;
            ldsm4(bh0, bh1, bh2, bh3, sb + S2_WHI + rb * 4352 + ks * 32 + b_off);
            ldsm4(bl0, bl1, bl2, bl3, sb + S2_WLO + rb * 4352 + ks * 32 + b_off);
            int nt = 2 * rb;
            mma16816(d1[nt], ah0, ah1, ah2, ah3, bh0, bh1);
            mma16816(d1[nt], al0, al1, al2, al3, bh0, bh1);
            mma16816(d1[nt], ah0, ah1, ah2, ah3, bl0, bl1);
            if (rb < 2) {
                mma16816(d1[nt + 1], ah0, ah1, ah2, ah3, bh2, bh3);
                mma16816(d1[nt + 1], al0, al1, al2, al3, bh2, bh3);
                mma16816(d1[nt + 1], ah0, ah1, ah2, ah3, bl2, bl3);
            }
        }
    }
    // ---- BN1 + ReLU -> L[px][49] ----
    #pragma unroll
    for (int nt = 0; nt < 5; nt++) {
        int pc0 = 8 * nt + 2 * tq, pc1 = pc0 + 1;
        float Aa = cA1[pc0], Ba = cB1[pc0];
        float Ab = cA1[pc1], Bb = cB1[pc1];
        L[(m0 + g) * 49 + pc0]     = fmaxf(fmaf(d1[nt][0], Aa, Ba), 0.f);
        L[(m0 + g) * 49 + pc1]     = fmaxf(fmaf(d1[nt][1], Ab, Bb), 0.f);
        L[(m0 + g + 8) * 49 + pc0] = fmaxf(fmaf(d1[nt][2], Aa, Ba), 0.f);
        L[(m0 + g + 8) * 49 + pc1] = fmaxf(fmaf(d1[nt][3], Ab, Bb), 0.f);
    }
    __syncthreads();

    // ---- softmax over k (9) for u = hh, hh+2 ----
    {
        const int px = t & 127;
        const int hh = t >> 7;
        const float* Lp = L + px * 49;
        #pragma unroll
        for (int uu = 0; uu < 2; uu++) {
            int u = hh + 2 * uu;
            float e[9], mx = -1e30f;
            #pragma unroll
            for (int k = 0; k < 9; k++) { e[k] = Lp[k * 4 + u]; mx = fmaxf(mx, e[k]); }
            float s = 0.f;
            #pragma unroll
            for (int k = 0; k < 9; k++) { float q = __expf(e[k] - mx); e[k] = q; s += q; }
            float inv = 1.f / s;
            #pragma unroll
            for (int k = 0; k < 9; k++) wts_s[px * 37 + k * 4 + u] = e[k] * inv;
        }
    }
    __syncthreads();

    // ---- coalesced dump to g_wts ----
    float4* gdst = (float4*)(g_wts + (size_t)(n * HW + p0) * Pp);
    for (int i4 = t; i4 < (128 * Pp) / 4; i4 += 256) {
        float4 v;
        int lin = i4 * 4;
        v.x = wts_s[(lin    ) / 36 * 37 + (lin    ) % 36];
        v.y = wts_s[(lin + 1) / 36 * 37 + (lin + 1) % 36];
        v.z = wts_s[(lin + 2) / 36 * 37 + (lin + 2) % 36];
        v.w = wts_s[(lin + 3) / 36 * 37 + (lin + 3) % 36];
        gdst[i4] = v;
    }
}

// ---------------------------------------------------------------------------
// Kernel 2: reassembly + pixelshuffle, 3-stage cp.async pipeline.
// ---------------------------------------------------------------------------
__device__ __forceinline__ void cp_async16(u32 dst, const void* src, u32 srcsz) {
    asm volatile("cp.async.cg.shared.global [%0], [%1], 16, %2;"
                 :: "r"(dst), "l"(src), "r"(srcsz));
}
__device__ __forceinline__ void cp_commit() { asm volatile("cp.async.commit_group;"); }
__device__ __forceinline__ void cp_wait1() { asm volatile("cp.async.wait_group 1;" ::: "memory"); }
__device__ __forceinline__ void cp_wait0() { asm volatile("cp.async.wait_group 0;" ::: "memory"); }
__device__ __forceinline__ void stcs2(float* p, float2 v) {
    asm volatile("st.global.cs.v2.f32 [%0], {%1,%2};" :: "l"(p), "f"(v.x), "f"(v.y));
}

#define ROWF    40
#define CHUNK_B (8 * 10 * ROWF * 4)   // 12800 B

extern "C" __global__ void __launch_bounds__(256)
k_reassemble(const float* __restrict__ x, float* __restrict__ out)
{
    __shared__ float xs[3][8][10][ROWF];

    const int tid = threadIdx.x;
    const int tx   = tid & 31;
    const int warp = tid >> 5;
    const int w0p = blockIdx.x * 32;
    const int h0  = blockIdx.y * 8;
    const int n   = blockIdx.z >> 3;
    const int c0  = (blockIdx.z & 7) * 32;
    const int h   = h0 + warp;
    const int w   = w0p + tx;

    const float* xb = x + (size_t)n * Cc * HW;
    u32 s_base = (u32)__cvta_generic_to_shared(&xs[0][0][0][0]);

    const float* gWarp = xb + (size_t)(c0 + warp) * HW + (h0 - 1) * Ww + (w0p - 4);
    u32  smOff[4];
    int  gOff[4];
    bool pred[4], act[4];
    #pragma unroll
    for (int i = 0; i < 4; i++) {
        int idx = i * 32 + tx;
        act[i] = idx < 100;
        int row = idx / 10, j = idx - row * 10;
        int v = w0p - 4 + 4 * j;
        bool rok = ((unsigned)(h0 - 1 + row) < (unsigned)Hh);
        bool cok = ((unsigned)v <= 60u);
        pred[i]  = act[i] && rok && cok;
        smOff[i] = (u32)((warp * 10 * ROWF + row * ROWF + 4 * j) * 4);
        gOff[i]  = row * Ww + 4 * j;
    }

    // prefetch chunks 0 and 1 (two commit groups)
    #pragma unroll
    for (int c = 0; c < 2; c++) {
        const float* gch = gWarp + (size_t)c * 8 * HW;
        u32 sb2 = s_base + c * CHUNK_B;
        #pragma unroll
        for (int i = 0; i < 4; i++)
            if (act[i]) cp_async16(sb2 + smOff[i], pred[i] ? gch + gOff[i] : xb,
                                   pred[i] ? 16u : 0u);
        cp_commit();
    }

    const float4* wp4 = (const float4*)(g_wts + (size_t)(n * HW + h * Ww + w) * Pp);
    u64 wp01[9], wp23[9];
    #pragma unroll
    for (int k = 0; k < 9; k++) {
        float4 v = __ldg(wp4 + k);
        wp01[k] = pack2(v.x, v.y);
        wp23[k] = pack2(v.z, v.w);
    }

    const int ty = warp;
    float* op = out + (size_t)n * Cc * (HW * 4)
                    + (size_t)c0 * (HW * 4) + (2 * h) * 128 + 2 * w;

    #pragma unroll 1
    for (int ch8 = 0; ch8 < 4; ch8++) {
        if (ch8 == 3) cp_wait0(); else cp_wait1();
        __syncthreads();

        if (ch8 < 2) {
            const float* gch = gWarp + (size_t)(ch8 + 2) * 8 * HW;
            u32 sb2 = s_base + ((ch8 + 2) % 3) * CHUNK_B;
            #pragma unroll
            for (int i = 0; i < 4; i++)
                if (act[i]) cp_async16(sb2 + smOff[i], pred[i] ? gch + gOff[i] : xb,
                                       pred[i] ? 16u : 0u);
            cp_commit();
        }

        const int b = ch8 % 3;
        #pragma unroll
        for (int cl = 0; cl < 8; cl++) {
            u64 a01 = 0ULL, a23 = 0ULL;
            #pragma unroll
            for (int dy = 0; dy < 3; dy++) {
                #pragma unroll
                for (int dx = 0; dx < 3; dx++) {
                    float xv = xs[b][cl][ty + dy][tx + 3 + dx];
                    u64 xp = pack2(xv, xv);
                    int k = dy * 3 + dx;
                    fma2(a01, xp, wp01[k]);
                    fma2(a23, xp, wp23[k]);
                }
            }
            stcs2(op,       unpack2(a01));
            stcs2(op + 128, unpack2(a23));
            op += HW * 4;
        }
    }
}

extern "C" void kernel_launch(void* const* d_in, const int* in_sizes, int n_in,
                              void* d_out, int out_size)
{
    const float* x     = (const float*)d_in[0];
    const float* w0    = (const float*)d_in[1];
    const float* b0    = (const float*)d_in[2];
    const float* bn0_g = (const float*)d_in[3];
    const float* bn0_b = (const float*)d_in[4];
    const float* bn0_m = (const float*)d_in[5];
    const float* bn0_v = (const float*)d_in[6];
    const float* w1    = (const float*)d_in[7];
    const float* b1    = (const float*)d_in[8];
    const float* bn1_g = (const float*)d_in[9];
    const float* bn1_b = (const float*)d_in[10];
    const float* bn1_m = (const float*)d_in[11];
    const float* bn1_v = (const float*)d_in[12];
    float* out = (float*)d_out;

    cudaFuncSetAttribute(k_weights, cudaFuncAttributeMaxDynamicSharedMemorySize, SMEM1);
    dim3 g1(32, Nn);
    k_weights<<<g1, 256, SMEM1>>>(x, w0, b0, bn0_g, bn0_b, bn0_m, bn0_v,
                                  w1, b1, bn1_g, bn1_b, bn1_m, bn1_v);

    dim3 g2(2, 8, Nn * 8);
    k_reassemble<<<g2, 256>>>(x, out);
}